// round 13
// baseline (speedup 1.0000x reference)
#include <cuda_runtime.h>
#include <cuda_bf16.h>
#include <cuda_fp16.h>
#include <cstdint>

// ---------------- problem constants ----------------
#define B      8
#define NV     4096
#define NLL    256
#define V_DIM  1024
#define L_DIM  768
#define EMBED  1024
#define HEADS  16
#define HD     64
#define SCALE  0.125f

typedef unsigned long long u64;
typedef unsigned int u32;

// ---------------- scratch (fp16 end-to-end) ----------------
__device__ __align__(256) __half g_vh[(size_t)B * NV * V_DIM];
__device__ __align__(256) __half g_lh[(size_t)B * NLL * L_DIM];
__device__ __align__(256) __half g_wv[EMBED * V_DIM];
__device__ __align__(256) __half g_wl[EMBED * L_DIM];
__device__ __align__(256) __half g_wvl[EMBED * L_DIM];
__device__ __align__(256) __half g_wo[V_DIM * EMBED];
__device__ __align__(256) __half g_q[(size_t)B * NV * EMBED];
__device__ __align__(256) __half g_k[(size_t)B * NLL * EMBED];
__device__ __align__(256) __half g_val[(size_t)B * NLL * EMBED];
__device__ __align__(256) __half g_att[(size_t)B * NV * EMBED];

// ---------------- helpers ----------------
__device__ __forceinline__ void mma_f16(float d[4], u32 a0, u32 a1, u32 a2, u32 a3,
                                        u32 b0, u32 b1) {
    asm volatile(
        "mma.sync.aligned.m16n8k16.row.col.f32.f16.f16.f32 "
        "{%0,%1,%2,%3}, {%4,%5,%6,%7}, {%8,%9}, {%0,%1,%2,%3};"
        : "+f"(d[0]), "+f"(d[1]), "+f"(d[2]), "+f"(d[3])
        : "r"(a0), "r"(a1), "r"(a2), "r"(a3), "r"(b0), "r"(b1));
}
__device__ __forceinline__ void ldsm4(u32& r0, u32& r1, u32& r2, u32& r3, u32 addr) {
    asm volatile("ldmatrix.sync.aligned.m8n8.x4.shared.b16 {%0,%1,%2,%3}, [%4];"
                 : "=r"(r0), "=r"(r1), "=r"(r2), "=r"(r3) : "r"(addr));
}
__device__ __forceinline__ u32 f22u(float x, float y) {
    __half2 h = __float22half2_rn(make_float2(x, y));
    return *(u32*)&h;
}
__device__ __forceinline__ u32 smem_u32(const void* p) {
    u32 a;
    asm("{ .reg .u64 t; cvta.to.shared.u64 t, %1; cvt.u32.u64 %0, t; }"
        : "=r"(a) : "l"(p));
    return a;
}
__device__ __forceinline__ void cp16(u32 dst, const void* src) {
    asm volatile("cp.async.cg.shared.global [%0], [%1], 16;"
                 :: "r"(dst), "l"(src) : "memory");
}
__device__ __forceinline__ void cp_commit() {
    asm volatile("cp.async.commit_group;" ::: "memory");
}
template<int N>
__device__ __forceinline__ void cp_wait() {
    asm volatile("cp.async.wait_group %0;" :: "n"(N) : "memory");
}

// ---------------- pre-convert fp32 -> fp16 ----------------
__global__ __launch_bounds__(256)
void cvt_f2h(const float* __restrict__ in, __half* __restrict__ out, int n)
{
    int i = (blockIdx.x * 256 + threadIdx.x) * 4;
    if (i < n) {
        float4 f = *(const float4*)(in + i);
        *(__half2*)(out + i)     = __float22half2_rn(make_float2(f.x, f.y));
        *(__half2*)(out + i + 2) = __float22half2_rn(make_float2(f.z, f.w));
    }
}

// ---------------- fp16 GEMM: cp.async 3-stage + ldmatrix ----------------
#define HSTR 40
#define TILE_HALF (128 * HSTR)
#define STAGE_HALF (2 * TILE_HALF)
#define STAGES 3
#define GSMEM (STAGES * STAGE_HALF * 2)

template<bool HALF_OUT>
__device__ __forceinline__
void gemm_h_body(const __half* __restrict__ A, const __half* __restrict__ Bw,
                 const float* __restrict__ bias, void* __restrict__ Cv,
                 int N, int K, float alpha, int bm, int bn)
{
    extern __shared__ __half hs[];
    const u32 sbase = smem_u32(hs);

    const int tid  = threadIdx.x;
    const int warp = tid >> 5;
    const int lane = tid & 31;
    const int wm = (warp >> 2) * 64;
    const int wn = (warp & 3) * 32;
    const int lq = lane >> 2;
    const int lr = lane & 3;

    // ldmatrix per-lane addressing: row (lane&15), col-half (lane>>4)*8
    const int mrow  = lane & 15;
    const int mcol8 = (lane >> 4) * 8;

    float acc[4][4][4];
#pragma unroll
    for (int i = 0; i < 4; i++)
#pragma unroll
        for (int j = 0; j < 4; j++)
#pragma unroll
            for (int r = 0; r < 4; r++) acc[i][j][r] = 0.f;

    const int row0 = tid >> 2;
    const int ch   = tid & 3;
    const __half* Ab = A  + (size_t)bm * K + ch * 8;
    const __half* Bb = Bw + (size_t)bn * K + ch * 8;

    const int NK = K / 32;

#define LOAD_STAGE(kt, s)                                                      \
    {                                                                          \
        const int _kh = (kt) * 32;                                             \
        _Pragma("unroll")                                                      \
        for (int _i = 0; _i < 2; _i++) {                                       \
            const int _r = row0 + _i * 64;                                     \
            cp16(sbase + ((s) * STAGE_HALF + _r * HSTR + ch * 8) * 2,          \
                 Ab + (size_t)_r * K + _kh);                                   \
            cp16(sbase + ((s) * STAGE_HALF + TILE_HALF + _r * HSTR + ch * 8) * 2, \
                 Bb + (size_t)_r * K + _kh);                                   \
        }                                                                      \
        cp_commit();                                                           \
    }

    LOAD_STAGE(0, 0)
    LOAD_STAGE(1, 1)

    for (int kt = 0; kt < NK; kt++) {
        cp_wait<STAGES - 2>();
        __syncthreads();
        if (kt + 2 < NK) LOAD_STAGE(kt + 2, (kt + 2) % STAGES)

        const u32 stA = sbase + ((kt % STAGES) * STAGE_HALF) * 2;
        const u32 stB = stA + TILE_HALF * 2;
#pragma unroll
        for (int ks = 0; ks < 2; ks++) {
            const int kk = ks * 16 + mcol8;
            u32 a[4][4];
#pragma unroll
            for (int mt = 0; mt < 4; mt++)
                ldsm4(a[mt][0], a[mt][1], a[mt][2], a[mt][3],
                      stA + ((wm + mt * 16 + mrow) * HSTR + kk) * 2);
            u32 b[4][2];
#pragma unroll
            for (int p = 0; p < 2; p++)
                ldsm4(b[2 * p][0], b[2 * p + 1][0], b[2 * p][1], b[2 * p + 1][1],
                      stB + ((wn + p * 16 + mrow) * HSTR + kk) * 2);
#pragma unroll
            for (int mt = 0; mt < 4; mt++)
#pragma unroll
                for (int nt = 0; nt < 4; nt++)
                    mma_f16(acc[mt][nt], a[mt][0], a[mt][1], a[mt][2], a[mt][3],
                            b[nt][0], b[nt][1]);
        }
        __syncthreads();
    }

    // epilogue
#pragma unroll
    for (int mt = 0; mt < 4; mt++) {
#pragma unroll
        for (int nt = 0; nt < 4; nt++) {
            const int r0 = bm + wm + mt * 16 + lq;
            const int c0 = bn + wn + nt * 8 + (lr << 1);
            const float bv0 = bias[c0];
            const float bv1 = bias[c0 + 1];
            const float o00 = alpha * (acc[mt][nt][0] + bv0);
            const float o01 = alpha * (acc[mt][nt][1] + bv1);
            const float o10 = alpha * (acc[mt][nt][2] + bv0);
            const float o11 = alpha * (acc[mt][nt][3] + bv1);
            if (HALF_OUT) {
                __half* C = (__half*)Cv;
                *(u32*)(C + (size_t)r0 * N + c0)       = f22u(o00, o01);
                *(u32*)(C + (size_t)(r0 + 8) * N + c0) = f22u(o10, o11);
            } else {
                float* C = (float*)Cv;
                *(float2*)(C + (size_t)r0 * N + c0)       = make_float2(o00, o01);
                *(float2*)(C + (size_t)(r0 + 8) * N + c0) = make_float2(o10, o11);
            }
        }
    }
#undef LOAD_STAGE
}

__global__ __launch_bounds__(256, 2)
void gemm_h_half(const __half* __restrict__ A, const __half* __restrict__ Bw,
                 const float* __restrict__ bias, __half* __restrict__ C,
                 int N, int K, float alpha)
{
    gemm_h_body<true>(A, Bw, bias, C, N, K, alpha,
                      blockIdx.y * 128, blockIdx.x * 128);
}

__global__ __launch_bounds__(256, 2)
void gemm_h_float(const __half* __restrict__ A, const __half* __restrict__ Bw,
                  const float* __restrict__ bias, float* __restrict__ C,
                  int N, int K, float alpha)
{
    gemm_h_body<false>(A, Bw, bias, C, N, K, alpha,
                       blockIdx.y * 128, blockIdx.x * 128);
}

__global__ __launch_bounds__(256, 2)
void gemm_h_dual(const __half* __restrict__ A,
                 const __half* __restrict__ W1, const float* __restrict__ b1,
                 __half* __restrict__ C1,
                 const __half* __restrict__ W2, const float* __restrict__ b2,
                 __half* __restrict__ C2,
                 int N, int K)
{
    const __half* Bw  = blockIdx.z ? W2 : W1;
    const float*  bia = blockIdx.z ? b2 : b1;
    __half*       C   = blockIdx.z ? C2 : C1;
    gemm_h_body<true>(A, Bw, bia, C, N, K, 1.f,
                      blockIdx.y * 128, blockIdx.x * 128);
}

// ---------------- tensor-core flash attention (fp16 in/out, R12 proven) ----------------
#define QSPLIT   4
#define QROWS    (NV / QSPLIT)
#define AT_KSTR  72
#define AT_VSTR  264
#define AT_SM_K  0
#define AT_SM_V  (256 * AT_KSTR * 2)
#define AT_SM_M  (AT_SM_V + 64 * AT_VSTR * 2)
#define AT_SMEM  (AT_SM_M + NLL * 4)

__global__ __launch_bounds__(256)
void attn_mma(const __half* __restrict__ q, const __half* __restrict__ kmat,
              const __half* __restrict__ vmat, const int* __restrict__ mask,
              __half* __restrict__ out)
{
    extern __shared__ char asmem[];
    __half* Ks = (__half*)(asmem + AT_SM_K);
    __half* Vt = (__half*)(asmem + AT_SM_V);
    float*  msf = (float*)(asmem + AT_SM_M);

    const int bh   = blockIdx.x;
    const int b    = bh >> 4;
    const int h    = bh & 15;
    const int sp   = blockIdx.y;
    const int tid  = threadIdx.x;
    const int warp = tid >> 5;
    const int lane = tid & 31;
    const int lq   = lane >> 2;
    const int lr   = lane & 3;

    for (int i = tid; i < 256 * 16; i += 256) {
        const int row = i >> 4;
        const int c4  = (i & 15) << 2;
        const size_t g = ((size_t)(b * NLL + row)) * EMBED + h * HD + c4;
        __half2 k0 = *(const __half2*)(kmat + g);
        __half2 k1 = *(const __half2*)(kmat + g + 2);
        __half2 v0 = *(const __half2*)(vmat + g);
        __half2 v1 = *(const __half2*)(vmat + g + 2);
        *(__half2*)(Ks + row * AT_KSTR + c4)     = k0;
        *(__half2*)(Ks + row * AT_KSTR + c4 + 2) = k1;
        Vt[(c4 + 0) * AT_VSTR + row] = __low2half(v0);
        Vt[(c4 + 1) * AT_VSTR + row] = __high2half(v0);
        Vt[(c4 + 2) * AT_VSTR + row] = __low2half(v1);
        Vt[(c4 + 3) * AT_VSTR + row] = __high2half(v1);
    }
    for (int i = tid; i < NLL; i += 256) msf[i] = mask[b * NLL + i] ? 1.f : 0.f;
    __syncthreads();

    for (int it = 0; it < QROWS / (16 * 8); it++) {
        const int r0 = sp * QROWS + (it * 8 + warp) * 16;
        const __half* qbase = q + ((size_t)(b * NV + r0)) * EMBED + h * HD;

        u32 qa[4][4];
#pragma unroll
        for (int c = 0; c < 4; c++) {
            const __half* p0 = qbase + (size_t)lq * EMBED + c * 16 + 2 * lr;
            const __half* p1 = qbase + (size_t)(lq + 8) * EMBED + c * 16 + 2 * lr;
            qa[c][0] = *(const u32*)(p0);
            qa[c][1] = *(const u32*)(p1);
            qa[c][2] = *(const u32*)(p0 + 8);
            qa[c][3] = *(const u32*)(p1 + 8);
        }

        float o[8][4];
#pragma unroll
        for (int jt = 0; jt < 8; jt++)
#pragma unroll
            for (int r = 0; r < 4; r++) o[jt][r] = 0.f;
        float sum0 = 0.f, sum1 = 0.f;

        for (int kb = 0; kb < 16; kb++) {
            float s0[4] = {0.f, 0.f, 0.f, 0.f};
            float s1[4] = {0.f, 0.f, 0.f, 0.f};
            const __half* kr = Ks + (kb * 16) * AT_KSTR;
#pragma unroll
            for (int c = 0; c < 4; c++) {
                u32 b0 = *(const u32*)(kr + lq * AT_KSTR + c * 16 + 2 * lr);
                u32 b1 = *(const u32*)(kr + lq * AT_KSTR + c * 16 + 2 * lr + 8);
                mma_f16(s0, qa[c][0], qa[c][1], qa[c][2], qa[c][3], b0, b1);
                u32 b2 = *(const u32*)(kr + (8 + lq) * AT_KSTR + c * 16 + 2 * lr);
                u32 b3 = *(const u32*)(kr + (8 + lq) * AT_KSTR + c * 16 + 2 * lr + 8);
                mma_f16(s1, qa[c][0], qa[c][1], qa[c][2], qa[c][3], b2, b3);
            }
            const int colb = kb * 16;
            const float m0 = msf[colb + 2 * lr];
            const float m1 = msf[colb + 2 * lr + 1];
            const float m2 = msf[colb + 8 + 2 * lr];
            const float m3 = msf[colb + 8 + 2 * lr + 1];
            const float p00 = __expf(s0[0]) * m0, p01 = __expf(s0[1]) * m1;
            const float p02 = __expf(s0[2]) * m0, p03 = __expf(s0[3]) * m1;
            const float p10 = __expf(s1[0]) * m2, p11 = __expf(s1[1]) * m3;
            const float p12 = __expf(s1[2]) * m2, p13 = __expf(s1[3]) * m3;
            sum0 += (p00 + p01) + (p10 + p11);
            sum1 += (p02 + p03) + (p12 + p13);
            const u32 a0 = f22u(p00, p01);
            const u32 a1 = f22u(p02, p03);
            const u32 a2 = f22u(p10, p11);
            const u32 a3 = f22u(p12, p13);

            const __half* vr = Vt + kb * 16;
#pragma unroll
            for (int jt = 0; jt < 8; jt++) {
                u32 vb0 = *(const u32*)(vr + (jt * 8 + lq) * AT_VSTR + 2 * lr);
                u32 vb1 = *(const u32*)(vr + (jt * 8 + lq) * AT_VSTR + 2 * lr + 8);
                mma_f16(o[jt], a0, a1, a2, a3, vb0, vb1);
            }
        }

        sum0 += __shfl_xor_sync(0xffffffffu, sum0, 1);
        sum0 += __shfl_xor_sync(0xffffffffu, sum0, 2);
        sum1 += __shfl_xor_sync(0xffffffffu, sum1, 1);
        sum1 += __shfl_xor_sync(0xffffffffu, sum1, 2);
        const float inv0 = __fdividef(1.f, sum0);
        const float inv1 = __fdividef(1.f, sum1);

        __half* ob = out + ((size_t)(b * NV + r0)) * EMBED + h * HD;
#pragma unroll
        for (int jt = 0; jt < 8; jt++) {
            *(u32*)(ob + (size_t)lq * EMBED + jt * 8 + 2 * lr)
                = f22u(o[jt][0] * inv0, o[jt][1] * inv0);
            *(u32*)(ob + (size_t)(lq + 8) * EMBED + jt * 8 + 2 * lr)
                = f22u(o[jt][2] * inv1, o[jt][3] * inv1);
        }
    }
}

// ---------------- launch ----------------
extern "C" void kernel_launch(void* const* d_in, const int* in_sizes, int n_in,
                              void* d_out, int out_size)
{
    const float* v     = (const float*)d_in[0];
    const float* l     = (const float*)d_in[1];
    const int*   amask = (const int*)  d_in[2];
    const float* w_v   = (const float*)d_in[3];
    const float* b_v   = (const float*)d_in[4];
    const float* w_l   = (const float*)d_in[5];
    const float* b_l   = (const float*)d_in[6];
    const float* w_vl  = (const float*)d_in[7];
    const float* b_vl  = (const float*)d_in[8];
    const float* w_out = (const float*)d_in[9];
    const float* b_out = (const float*)d_in[10];
    float* out = (float*)d_out;

    __half *vh, *lh, *wv, *wl, *wvl, *wo, *q, *k, *val, *att;
    cudaGetSymbolAddress((void**)&vh,  g_vh);
    cudaGetSymbolAddress((void**)&lh,  g_lh);
    cudaGetSymbolAddress((void**)&wv,  g_wv);
    cudaGetSymbolAddress((void**)&wl,  g_wl);
    cudaGetSymbolAddress((void**)&wvl, g_wvl);
    cudaGetSymbolAddress((void**)&wo,  g_wo);
    cudaGetSymbolAddress((void**)&q,   g_q);
    cudaGetSymbolAddress((void**)&k,   g_k);
    cudaGetSymbolAddress((void**)&val, g_val);
    cudaGetSymbolAddress((void**)&att, g_att);

    cudaFuncSetAttribute(attn_mma, cudaFuncAttributeMaxDynamicSharedMemorySize, AT_SMEM);
    cudaFuncSetAttribute(gemm_h_half, cudaFuncAttributeMaxDynamicSharedMemorySize, GSMEM);
    cudaFuncSetAttribute(gemm_h_float, cudaFuncAttributeMaxDynamicSharedMemorySize, GSMEM);
    cudaFuncSetAttribute(gemm_h_dual, cudaFuncAttributeMaxDynamicSharedMemorySize, GSMEM);

    const int nv_ = B * NV * V_DIM, nl_ = B * NLL * L_DIM;
    cvt_f2h<<<(nv_ / 4 + 255) / 256, 256>>>(v, vh, nv_);
    cvt_f2h<<<(nl_ / 4 + 255) / 256, 256>>>(l, lh, nl_);
    cvt_f2h<<<(EMBED * V_DIM / 4 + 255) / 256, 256>>>(w_v, wv, EMBED * V_DIM);
    cvt_f2h<<<(EMBED * L_DIM / 4 + 255) / 256, 256>>>(w_l, wl, EMBED * L_DIM);
    cvt_f2h<<<(EMBED * L_DIM / 4 + 255) / 256, 256>>>(w_vl, wvl, EMBED * L_DIM);
    cvt_f2h<<<(V_DIM * EMBED / 4 + 255) / 256, 256>>>(w_out, wo, V_DIM * EMBED);

    gemm_h_half<<<dim3(EMBED / 128, (B * NV) / 128), 256, GSMEM>>>(
        vh, wv, b_v, q, EMBED, V_DIM, SCALE);
    gemm_h_dual<<<dim3(EMBED / 128, (B * NLL) / 128, 2), 256, GSMEM>>>(
        lh, wl, b_l, k, wvl, b_vl, val, EMBED, L_DIM);
    attn_mma<<<dim3(B * HEADS, QSPLIT), 256, AT_SMEM>>>(q, k, val, amask, att);
    gemm_h_float<<<dim3(V_DIM / 128, (B * NV) / 128), 256, GSMEM>>>(
        att, wo, b_out, out, V_DIM, EMBED, 1.f);
}

// round 14
// speedup vs baseline: 1.0093x; 1.0093x over previous
#include <cuda_runtime.h>
#include <cuda_bf16.h>
#include <cuda_fp16.h>
#include <cstdint>

// ---------------- problem constants ----------------
#define B      8
#define NV     4096
#define NLL    256
#define V_DIM  1024
#define L_DIM  768
#define EMBED  1024
#define HEADS  16
#define HD     64
#define SCALE  0.125f

typedef unsigned long long u64;
typedef unsigned int u32;

// ---------------- scratch (fp16 end-to-end) ----------------
__device__ __align__(256) __half g_vh[(size_t)B * NV * V_DIM];
__device__ __align__(256) __half g_lh[(size_t)B * NLL * L_DIM];
__device__ __align__(256) __half g_wv[EMBED * V_DIM];
__device__ __align__(256) __half g_wl[EMBED * L_DIM];
__device__ __align__(256) __half g_wvl[EMBED * L_DIM];
__device__ __align__(256) __half g_wo[V_DIM * EMBED];
__device__ __align__(256) __half g_q[(size_t)B * NV * EMBED];
__device__ __align__(256) __half g_k[(size_t)B * NLL * EMBED];
__device__ __align__(256) __half g_val[(size_t)B * NLL * EMBED];
__device__ __align__(256) __half g_att[(size_t)B * NV * EMBED];

// ---------------- helpers ----------------
__device__ __forceinline__ void mma_f16(float d[4], u32 a0, u32 a1, u32 a2, u32 a3,
                                        u32 b0, u32 b1) {
    asm volatile(
        "mma.sync.aligned.m16n8k16.row.col.f32.f16.f16.f32 "
        "{%0,%1,%2,%3}, {%4,%5,%6,%7}, {%8,%9}, {%0,%1,%2,%3};"
        : "+f"(d[0]), "+f"(d[1]), "+f"(d[2]), "+f"(d[3])
        : "r"(a0), "r"(a1), "r"(a2), "r"(a3), "r"(b0), "r"(b1));
}
__device__ __forceinline__ u32 f22u(float x, float y) {
    __half2 h = __float22half2_rn(make_float2(x, y));
    return *(u32*)&h;
}
__device__ __forceinline__ u32 smem_u32(const void* p) {
    u32 a;
    asm("{ .reg .u64 t; cvta.to.shared.u64 t, %1; cvt.u32.u64 %0, t; }"
        : "=r"(a) : "l"(p));
    return a;
}
__device__ __forceinline__ void cp16(u32 dst, const void* src) {
    asm volatile("cp.async.cg.shared.global [%0], [%1], 16;"
                 :: "r"(dst), "l"(src) : "memory");
}
__device__ __forceinline__ void cp_commit() {
    asm volatile("cp.async.commit_group;" ::: "memory");
}
template<int N>
__device__ __forceinline__ void cp_wait() {
    asm volatile("cp.async.wait_group %0;" :: "n"(N) : "memory");
}

// ---------------- pre-convert fp32 -> fp16 ----------------
__global__ __launch_bounds__(256)
void cvt_f2h(const float* __restrict__ in, __half* __restrict__ out, int n)
{
    int i = (blockIdx.x * 256 + threadIdx.x) * 4;
    if (i < n) {
        float4 f = *(const float4*)(in + i);
        *(__half2*)(out + i)     = __float22half2_rn(make_float2(f.x, f.y));
        *(__half2*)(out + i + 2) = __float22half2_rn(make_float2(f.z, f.w));
    }
}

// ---------------- fp16 GEMM: cp.async 4-stage, ONE sync per ktile ----------------
#define HSTR 40
#define TILE_HALF (128 * HSTR)
#define STAGE_HALF (2 * TILE_HALF)
#define STAGES 4
#define GSMEM (STAGES * STAGE_HALF * 2)   // 81920 bytes

template<bool HALF_OUT>
__device__ __forceinline__
void gemm_h_body(const __half* __restrict__ A, const __half* __restrict__ Bw,
                 const float* __restrict__ bias, void* __restrict__ Cv,
                 int N, int K, float alpha, int bm, int bn)
{
    extern __shared__ __half hs[];
    const u32 sbase = smem_u32(hs);

    const int tid  = threadIdx.x;
    const int warp = tid >> 5;
    const int lane = tid & 31;
    const int wm = (warp >> 2) * 64;
    const int wn = (warp & 3) * 32;
    const int lq = lane >> 2;
    const int lr = lane & 3;

    float acc[4][4][4];
#pragma unroll
    for (int i = 0; i < 4; i++)
#pragma unroll
        for (int j = 0; j < 4; j++)
#pragma unroll
            for (int r = 0; r < 4; r++) acc[i][j][r] = 0.f;

    const int row0 = tid >> 2;
    const int ch   = tid & 3;
    const __half* Ab = A  + (size_t)bm * K + ch * 8;
    const __half* Bb = Bw + (size_t)bn * K + ch * 8;

    const int NK = K / 32;

#define LOAD_STAGE(kt, s)                                                      \
    {                                                                          \
        const int _kh = (kt) * 32;                                             \
        _Pragma("unroll")                                                      \
        for (int _i = 0; _i < 2; _i++) {                                       \
            const int _r = row0 + _i * 64;                                     \
            cp16(sbase + ((s) * STAGE_HALF + _r * HSTR + ch * 8) * 2,          \
                 Ab + (size_t)_r * K + _kh);                                   \
            cp16(sbase + ((s) * STAGE_HALF + TILE_HALF + _r * HSTR + ch * 8) * 2, \
                 Bb + (size_t)_r * K + _kh);                                   \
        }                                                                      \
        cp_commit();                                                           \
    }

    LOAD_STAGE(0, 0)
    LOAD_STAGE(1, 1)
    LOAD_STAGE(2, 2)

    for (int kt = 0; kt < NK; kt++) {
        cp_wait<2>();          // stage kt arrived (<=2 younger groups pending)
        __syncthreads();       // also: all warps done reading stage (kt-1)%4
        if (kt + 3 < NK) LOAD_STAGE(kt + 3, (kt + 3) % STAGES)

        const __half* As = hs + (kt % STAGES) * STAGE_HALF;
        const __half* Bs = As + TILE_HALF;
#pragma unroll
        for (int ks = 0; ks < 2; ks++) {
            const int kk = ks * 16;
            u32 a[4][4];
#pragma unroll
            for (int mt = 0; mt < 4; mt++) {
                const int r = wm + mt * 16 + lq;
                a[mt][0] = *(const u32*)(As + r * HSTR + kk + 2 * lr);
                a[mt][1] = *(const u32*)(As + (r + 8) * HSTR + kk + 2 * lr);
                a[mt][2] = *(const u32*)(As + r * HSTR + kk + 2 * lr + 8);
                a[mt][3] = *(const u32*)(As + (r + 8) * HSTR + kk + 2 * lr + 8);
            }
            u32 b[4][2];
#pragma unroll
            for (int nt = 0; nt < 4; nt++) {
                const int c = wn + nt * 8 + lq;
                b[nt][0] = *(const u32*)(Bs + c * HSTR + kk + 2 * lr);
                b[nt][1] = *(const u32*)(Bs + c * HSTR + kk + 2 * lr + 8);
            }
#pragma unroll
            for (int mt = 0; mt < 4; mt++)
#pragma unroll
                for (int nt = 0; nt < 4; nt++)
                    mma_f16(acc[mt][nt], a[mt][0], a[mt][1], a[mt][2], a[mt][3],
                            b[nt][0], b[nt][1]);
        }
        // no bottom sync: 4 stages guarantee next iter's loads hit a free slot
    }

    // epilogue
#pragma unroll
    for (int mt = 0; mt < 4; mt++) {
#pragma unroll
        for (int nt = 0; nt < 4; nt++) {
            const int r0 = bm + wm + mt * 16 + lq;
            const int c0 = bn + wn + nt * 8 + (lr << 1);
            const float bv0 = bias[c0];
            const float bv1 = bias[c0 + 1];
            const float o00 = alpha * (acc[mt][nt][0] + bv0);
            const float o01 = alpha * (acc[mt][nt][1] + bv1);
            const float o10 = alpha * (acc[mt][nt][2] + bv0);
            const float o11 = alpha * (acc[mt][nt][3] + bv1);
            if (HALF_OUT) {
                __half* C = (__half*)Cv;
                *(u32*)(C + (size_t)r0 * N + c0)       = f22u(o00, o01);
                *(u32*)(C + (size_t)(r0 + 8) * N + c0) = f22u(o10, o11);
            } else {
                float* C = (float*)Cv;
                *(float2*)(C + (size_t)r0 * N + c0)       = make_float2(o00, o01);
                *(float2*)(C + (size_t)(r0 + 8) * N + c0) = make_float2(o10, o11);
            }
        }
    }
#undef LOAD_STAGE
}

__global__ __launch_bounds__(256, 2)
void gemm_h_half(const __half* __restrict__ A, const __half* __restrict__ Bw,
                 const float* __restrict__ bias, __half* __restrict__ C,
                 int N, int K, float alpha)
{
    gemm_h_body<true>(A, Bw, bias, C, N, K, alpha,
                      blockIdx.y * 128, blockIdx.x * 128);
}

__global__ __launch_bounds__(256, 2)
void gemm_h_float(const __half* __restrict__ A, const __half* __restrict__ Bw,
                  const float* __restrict__ bias, float* __restrict__ C,
                  int N, int K, float alpha)
{
    gemm_h_body<false>(A, Bw, bias, C, N, K, alpha,
                       blockIdx.y * 128, blockIdx.x * 128);
}

__global__ __launch_bounds__(256, 2)
void gemm_h_dual(const __half* __restrict__ A,
                 const __half* __restrict__ W1, const float* __restrict__ b1,
                 __half* __restrict__ C1,
                 const __half* __restrict__ W2, const float* __restrict__ b2,
                 __half* __restrict__ C2,
                 int N, int K)
{
    const __half* Bw  = blockIdx.z ? W2 : W1;
    const float*  bia = blockIdx.z ? b2 : b1;
    __half*       C   = blockIdx.z ? C2 : C1;
    gemm_h_body<true>(A, Bw, bia, C, N, K, 1.f,
                      blockIdx.y * 128, blockIdx.x * 128);
}

// ---------------- tensor-core flash attention (fp16 in/out, proven) ----------------
#define QSPLIT   4
#define QROWS    (NV / QSPLIT)
#define AT_KSTR  72
#define AT_VSTR  264
#define AT_SM_K  0
#define AT_SM_V  (256 * AT_KSTR * 2)
#define AT_SM_M  (AT_SM_V + 64 * AT_VSTR * 2)
#define AT_SMEM  (AT_SM_M + NLL * 4)

__global__ __launch_bounds__(256)
void attn_mma(const __half* __restrict__ q, const __half* __restrict__ kmat,
              const __half* __restrict__ vmat, const int* __restrict__ mask,
              __half* __restrict__ out)
{
    extern __shared__ char asmem[];
    __half* Ks = (__half*)(asmem + AT_SM_K);
    __half* Vt = (__half*)(asmem + AT_SM_V);
    float*  msf = (float*)(asmem + AT_SM_M);

    const int bh   = blockIdx.x;
    const int b    = bh >> 4;
    const int h    = bh & 15;
    const int sp   = blockIdx.y;
    const int tid  = threadIdx.x;
    const int warp = tid >> 5;
    const int lane = tid & 31;
    const int lq   = lane >> 2;
    const int lr   = lane & 3;

    for (int i = tid; i < 256 * 16; i += 256) {
        const int row = i >> 4;
        const int c4  = (i & 15) << 2;
        const size_t g = ((size_t)(b * NLL + row)) * EMBED + h * HD + c4;
        __half2 k0 = *(const __half2*)(kmat + g);
        __half2 k1 = *(const __half2*)(kmat + g + 2);
        __half2 v0 = *(const __half2*)(vmat + g);
        __half2 v1 = *(const __half2*)(vmat + g + 2);
        *(__half2*)(Ks + row * AT_KSTR + c4)     = k0;
        *(__half2*)(Ks + row * AT_KSTR + c4 + 2) = k1;
        Vt[(c4 + 0) * AT_VSTR + row] = __low2half(v0);
        Vt[(c4 + 1) * AT_VSTR + row] = __high2half(v0);
        Vt[(c4 + 2) * AT_VSTR + row] = __low2half(v1);
        Vt[(c4 + 3) * AT_VSTR + row] = __high2half(v1);
    }
    for (int i = tid; i < NLL; i += 256) msf[i] = mask[b * NLL + i] ? 1.f : 0.f;
    __syncthreads();

    for (int it = 0; it < QROWS / (16 * 8); it++) {
        const int r0 = sp * QROWS + (it * 8 + warp) * 16;
        const __half* qbase = q + ((size_t)(b * NV + r0)) * EMBED + h * HD;

        u32 qa[4][4];
#pragma unroll
        for (int c = 0; c < 4; c++) {
            const __half* p0 = qbase + (size_t)lq * EMBED + c * 16 + 2 * lr;
            const __half* p1 = qbase + (size_t)(lq + 8) * EMBED + c * 16 + 2 * lr;
            qa[c][0] = *(const u32*)(p0);
            qa[c][1] = *(const u32*)(p1);
            qa[c][2] = *(const u32*)(p0 + 8);
            qa[c][3] = *(const u32*)(p1 + 8);
        }

        float o[8][4];
#pragma unroll
        for (int jt = 0; jt < 8; jt++)
#pragma unroll
            for (int r = 0; r < 4; r++) o[jt][r] = 0.f;
        float sum0 = 0.f, sum1 = 0.f;

        for (int kb = 0; kb < 16; kb++) {
            float s0[4] = {0.f, 0.f, 0.f, 0.f};
            float s1[4] = {0.f, 0.f, 0.f, 0.f};
            const __half* kr = Ks + (kb * 16) * AT_KSTR;
#pragma unroll
            for (int c = 0; c < 4; c++) {
                u32 b0 = *(const u32*)(kr + lq * AT_KSTR + c * 16 + 2 * lr);
                u32 b1 = *(const u32*)(kr + lq * AT_KSTR + c * 16 + 2 * lr + 8);
                mma_f16(s0, qa[c][0], qa[c][1], qa[c][2], qa[c][3], b0, b1);
                u32 b2 = *(const u32*)(kr + (8 + lq) * AT_KSTR + c * 16 + 2 * lr);
                u32 b3 = *(const u32*)(kr + (8 + lq) * AT_KSTR + c * 16 + 2 * lr + 8);
                mma_f16(s1, qa[c][0], qa[c][1], qa[c][2], qa[c][3], b2, b3);
            }
            const int colb = kb * 16;
            const float m0 = msf[colb + 2 * lr];
            const float m1 = msf[colb + 2 * lr + 1];
            const float m2 = msf[colb + 8 + 2 * lr];
            const float m3 = msf[colb + 8 + 2 * lr + 1];
            const float p00 = __expf(s0[0]) * m0, p01 = __expf(s0[1]) * m1;
            const float p02 = __expf(s0[2]) * m0, p03 = __expf(s0[3]) * m1;
            const float p10 = __expf(s1[0]) * m2, p11 = __expf(s1[1]) * m3;
            const float p12 = __expf(s1[2]) * m2, p13 = __expf(s1[3]) * m3;
            sum0 += (p00 + p01) + (p10 + p11);
            sum1 += (p02 + p03) + (p12 + p13);
            const u32 a0 = f22u(p00, p01);
            const u32 a1 = f22u(p02, p03);
            const u32 a2 = f22u(p10, p11);
            const u32 a3 = f22u(p12, p13);

            const __half* vr = Vt + kb * 16;
#pragma unroll
            for (int jt = 0; jt < 8; jt++) {
                u32 vb0 = *(const u32*)(vr + (jt * 8 + lq) * AT_VSTR + 2 * lr);
                u32 vb1 = *(const u32*)(vr + (jt * 8 + lq) * AT_VSTR + 2 * lr + 8);
                mma_f16(o[jt], a0, a1, a2, a3, vb0, vb1);
            }
        }

        sum0 += __shfl_xor_sync(0xffffffffu, sum0, 1);
        sum0 += __shfl_xor_sync(0xffffffffu, sum0, 2);
        sum1 += __shfl_xor_sync(0xffffffffu, sum1, 1);
        sum1 += __shfl_xor_sync(0xffffffffu, sum1, 2);
        const float inv0 = __fdividef(1.f, sum0);
        const float inv1 = __fdividef(1.f, sum1);

        __half* ob = out + ((size_t)(b * NV + r0)) * EMBED + h * HD;
#pragma unroll
        for (int jt = 0; jt < 8; jt++) {
            *(u32*)(ob + (size_t)lq * EMBED + jt * 8 + 2 * lr)
                = f22u(o[jt][0] * inv0, o[jt][1] * inv0);
            *(u32*)(ob + (size_t)(lq + 8) * EMBED + jt * 8 + 2 * lr)
                = f22u(o[jt][2] * inv1, o[jt][3] * inv1);
        }
    }
}

// ---------------- launch ----------------
extern "C" void kernel_launch(void* const* d_in, const int* in_sizes, int n_in,
                              void* d_out, int out_size)
{
    const float* v     = (const float*)d_in[0];
    const float* l     = (const float*)d_in[1];
    const int*   amask = (const int*)  d_in[2];
    const float* w_v   = (const float*)d_in[3];
    const float* b_v   = (const float*)d_in[4];
    const float* w_l   = (const float*)d_in[5];
    const float* b_l   = (const float*)d_in[6];
    const float* w_vl  = (const float*)d_in[7];
    const float* b_vl  = (const float*)d_in[8];
    const float* w_out = (const float*)d_in[9];
    const float* b_out = (const float*)d_in[10];
    float* out = (float*)d_out;

    __half *vh, *lh, *wv, *wl, *wvl, *wo, *q, *k, *val, *att;
    cudaGetSymbolAddress((void**)&vh,  g_vh);
    cudaGetSymbolAddress((void**)&lh,  g_lh);
    cudaGetSymbolAddress((void**)&wv,  g_wv);
    cudaGetSymbolAddress((void**)&wl,  g_wl);
    cudaGetSymbolAddress((void**)&wvl, g_wvl);
    cudaGetSymbolAddress((void**)&wo,  g_wo);
    cudaGetSymbolAddress((void**)&q,   g_q);
    cudaGetSymbolAddress((void**)&k,   g_k);
    cudaGetSymbolAddress((void**)&val, g_val);
    cudaGetSymbolAddress((void**)&att, g_att);

    cudaFuncSetAttribute(attn_mma, cudaFuncAttributeMaxDynamicSharedMemorySize, AT_SMEM);
    cudaFuncSetAttribute(gemm_h_half, cudaFuncAttributeMaxDynamicSharedMemorySize, GSMEM);
    cudaFuncSetAttribute(gemm_h_float, cudaFuncAttributeMaxDynamicSharedMemorySize, GSMEM);
    cudaFuncSetAttribute(gemm_h_dual, cudaFuncAttributeMaxDynamicSharedMemorySize, GSMEM);

    const int nv_ = B * NV * V_DIM, nl_ = B * NLL * L_DIM;
    cvt_f2h<<<(nv_ / 4 + 255) / 256, 256>>>(v, vh, nv_);
    cvt_f2h<<<(nl_ / 4 + 255) / 256, 256>>>(l, lh, nl_);
    cvt_f2h<<<(EMBED * V_DIM / 4 + 255) / 256, 256>>>(w_v, wv, EMBED * V_DIM);
    cvt_f2h<<<(EMBED * L_DIM / 4 + 255) / 256, 256>>>(w_l, wl, EMBED * L_DIM);
    cvt_f2h<<<(EMBED * L_DIM / 4 + 255) / 256, 256>>>(w_vl, wvl, EMBED * L_DIM);
    cvt_f2h<<<(V_DIM * EMBED / 4 + 255) / 256, 256>>>(w_out, wo, V_DIM * EMBED);

    gemm_h_half<<<dim3(EMBED / 128, (B * NV) / 128), 256, GSMEM>>>(
        vh, wv, b_v, q, EMBED, V_DIM, SCALE);
    gemm_h_dual<<<dim3(EMBED / 128, (B * NLL) / 128, 2), 256, GSMEM>>>(
        lh, wl, b_l, k, wvl, b_vl, val, EMBED, L_DIM);
    attn_mma<<<dim3(B * HEADS, QSPLIT), 256, AT_SMEM>>>(q, k, val, amask, att);
    gemm_h_float<<<dim3(V_DIM / 128, (B * NV) / 128), 256, GSMEM>>>(
        att, wo, b_out, out, V_DIM, EMBED, 1.f);
}

// round 15
// speedup vs baseline: 1.0413x; 1.0317x over previous
#include <cuda_runtime.h>
#include <cuda_bf16.h>
#include <cuda_fp16.h>
#include <cstdint>

// ---------------- problem constants ----------------
#define B      8
#define NV     4096
#define NLL    256
#define V_DIM  1024
#define L_DIM  768
#define EMBED  1024
#define HEADS  16
#define HD     64
#define SCALE  0.125f

typedef unsigned long long u64;
typedef unsigned int u32;

// ---------------- scratch (fp16 end-to-end) ----------------
__device__ __align__(256) __half g_vh[(size_t)B * NV * V_DIM];
__device__ __align__(256) __half g_lh[(size_t)B * NLL * L_DIM];
__device__ __align__(256) __half g_wv[EMBED * V_DIM];
__device__ __align__(256) __half g_wl[EMBED * L_DIM];
__device__ __align__(256) __half g_wvl[EMBED * L_DIM];
__device__ __align__(256) __half g_wo[V_DIM * EMBED];
__device__ __align__(256) __half g_q[(size_t)B * NV * EMBED];
__device__ __align__(256) __half g_k[(size_t)B * NLL * EMBED];
__device__ __align__(256) __half g_val[(size_t)B * NLL * EMBED];
__device__ __align__(256) __half g_att[(size_t)B * NV * EMBED];

// ---------------- helpers ----------------
__device__ __forceinline__ void mma_f16(float d[4], u32 a0, u32 a1, u32 a2, u32 a3,
                                        u32 b0, u32 b1) {
    asm volatile(
        "mma.sync.aligned.m16n8k16.row.col.f32.f16.f16.f32 "
        "{%0,%1,%2,%3}, {%4,%5,%6,%7}, {%8,%9}, {%0,%1,%2,%3};"
        : "+f"(d[0]), "+f"(d[1]), "+f"(d[2]), "+f"(d[3])
        : "r"(a0), "r"(a1), "r"(a2), "r"(a3), "r"(b0), "r"(b1));
}
__device__ __forceinline__ u32 f22u(float x, float y) {
    __half2 h = __float22half2_rn(make_float2(x, y));
    return *(u32*)&h;
}
__device__ __forceinline__ u32 smem_u32(const void* p) {
    u32 a;
    asm("{ .reg .u64 t; cvta.to.shared.u64 t, %1; cvt.u32.u64 %0, t; }"
        : "=r"(a) : "l"(p));
    return a;
}
__device__ __forceinline__ void cp16(u32 dst, const void* src) {
    asm volatile("cp.async.cg.shared.global [%0], [%1], 16;"
                 :: "r"(dst), "l"(src) : "memory");
}
__device__ __forceinline__ void cp_commit() {
    asm volatile("cp.async.commit_group;" ::: "memory");
}
template<int N>
__device__ __forceinline__ void cp_wait() {
    asm volatile("cp.async.wait_group %0;" :: "n"(N) : "memory");
}

// ---------------- fused pre-convert: all fp32 inputs -> fp16, one launch ----------------
#define NV_E   (B * NV * V_DIM)          // 33554432
#define NL_E   (B * NLL * L_DIM)         // 1572864
#define WV_E   (EMBED * V_DIM)           // 1048576
#define WL_E   (EMBED * L_DIM)           // 786432
#define CV0    (NV_E / 4)
#define CV1    (CV0 + NL_E / 4)
#define CV2    (CV1 + WV_E / 4)
#define CV3    (CV2 + WL_E / 4)
#define CV4    (CV3 + WL_E / 4)
#define CV5    (CV4 + WV_E / 4)          // total vec4 count

__global__ __launch_bounds__(256)
void cvt_all(const float* __restrict__ v,  const float* __restrict__ l,
             const float* __restrict__ wv, const float* __restrict__ wl,
             const float* __restrict__ wvl, const float* __restrict__ wo)
{
    int i = blockIdx.x * 256 + threadIdx.x;
    if (i >= CV5) return;
    const float* src; __half* dst; int base;
    if      (i < CV0) { src = v;   dst = g_vh;  base = 0;   }
    else if (i < CV1) { src = l;   dst = g_lh;  base = CV0; }
    else if (i < CV2) { src = wv;  dst = g_wv;  base = CV1; }
    else if (i < CV3) { src = wl;  dst = g_wl;  base = CV2; }
    else if (i < CV4) { src = wvl; dst = g_wvl; base = CV3; }
    else              { src = wo;  dst = g_wo;  base = CV4; }
    const int j = (i - base) * 4;
    float4 f = *(const float4*)(src + j);
    *(__half2*)(dst + j)     = __float22half2_rn(make_float2(f.x, f.y));
    *(__half2*)(dst + j + 2) = __float22half2_rn(make_float2(f.z, f.w));
}

// ---------------- fp16 GEMM body: cp.async 3-stage (R12 proven) ----------------
#define HSTR 40
#define TILE_HALF (128 * HSTR)
#define STAGE_HALF (2 * TILE_HALF)
#define STAGES 3
#define GSMEM (STAGES * STAGE_HALF * 2)   // 61440 bytes

template<bool HALF_OUT>
__device__ __forceinline__
void gemm_h_body(const __half* __restrict__ A, const __half* __restrict__ Bw,
                 const float* __restrict__ bias, void* __restrict__ Cv,
                 int N, int K, float alpha, int bm, int bn)
{
    extern __shared__ __half hs[];
    const u32 sbase = smem_u32(hs);

    const int tid  = threadIdx.x;
    const int warp = tid >> 5;
    const int lane = tid & 31;
    const int wm = (warp >> 2) * 64;
    const int wn = (warp & 3) * 32;
    const int lq = lane >> 2;
    const int lr = lane & 3;

    float acc[4][4][4];
#pragma unroll
    for (int i = 0; i < 4; i++)
#pragma unroll
        for (int j = 0; j < 4; j++)
#pragma unroll
            for (int r = 0; r < 4; r++) acc[i][j][r] = 0.f;

    const int row0 = tid >> 2;
    const int ch   = tid & 3;
    const __half* Ab = A  + (size_t)bm * K + ch * 8;
    const __half* Bb = Bw + (size_t)bn * K + ch * 8;

    const int NK = K / 32;

#define LOAD_STAGE(kt, s)                                                      \
    {                                                                          \
        const int _kh = (kt) * 32;                                             \
        _Pragma("unroll")                                                      \
        for (int _i = 0; _i < 2; _i++) {                                       \
            const int _r = row0 + _i * 64;                                     \
            cp16(sbase + ((s) * STAGE_HALF + _r * HSTR + ch * 8) * 2,          \
                 Ab + (size_t)_r * K + _kh);                                   \
            cp16(sbase + ((s) * STAGE_HALF + TILE_HALF + _r * HSTR + ch * 8) * 2, \
                 Bb + (size_t)_r * K + _kh);                                   \
        }                                                                      \
        cp_commit();                                                           \
    }

    LOAD_STAGE(0, 0)
    LOAD_STAGE(1, 1)

    for (int kt = 0; kt < NK; kt++) {
        cp_wait<STAGES - 2>();
        __syncthreads();
        if (kt + 2 < NK) LOAD_STAGE(kt + 2, (kt + 2) % STAGES)

        const __half* As = hs + (kt % STAGES) * STAGE_HALF;
        const __half* Bs = As + TILE_HALF;
#pragma unroll
        for (int ks = 0; ks < 2; ks++) {
            const int kk = ks * 16;
            u32 a[4][4];
#pragma unroll
            for (int mt = 0; mt < 4; mt++) {
                const int r = wm + mt * 16 + lq;
                a[mt][0] = *(const u32*)(As + r * HSTR + kk + 2 * lr);
                a[mt][1] = *(const u32*)(As + (r + 8) * HSTR + kk + 2 * lr);
                a[mt][2] = *(const u32*)(As + r * HSTR + kk + 2 * lr + 8);
                a[mt][3] = *(const u32*)(As + (r + 8) * HSTR + kk + 2 * lr + 8);
            }
            u32 b[4][2];
#pragma unroll
            for (int nt = 0; nt < 4; nt++) {
                const int c = wn + nt * 8 + lq;
                b[nt][0] = *(const u32*)(Bs + c * HSTR + kk + 2 * lr);
                b[nt][1] = *(const u32*)(Bs + c * HSTR + kk + 2 * lr + 8);
            }
#pragma unroll
            for (int mt = 0; mt < 4; mt++)
#pragma unroll
                for (int nt = 0; nt < 4; nt++)
                    mma_f16(acc[mt][nt], a[mt][0], a[mt][1], a[mt][2], a[mt][3],
                            b[nt][0], b[nt][1]);
        }
        __syncthreads();
    }

    // epilogue
#pragma unroll
    for (int mt = 0; mt < 4; mt++) {
#pragma unroll
        for (int nt = 0; nt < 4; nt++) {
            const int r0 = bm + wm + mt * 16 + lq;
            const int c0 = bn + wn + nt * 8 + (lr << 1);
            const float bv0 = bias[c0];
            const float bv1 = bias[c0 + 1];
            const float o00 = alpha * (acc[mt][nt][0] + bv0);
            const float o01 = alpha * (acc[mt][nt][1] + bv1);
            const float o10 = alpha * (acc[mt][nt][2] + bv0);
            const float o11 = alpha * (acc[mt][nt][3] + bv1);
            if (HALF_OUT) {
                __half* C = (__half*)Cv;
                *(u32*)(C + (size_t)r0 * N + c0)       = f22u(o00, o01);
                *(u32*)(C + (size_t)(r0 + 8) * N + c0) = f22u(o10, o11);
            } else {
                float* C = (float*)Cv;
                *(float2*)(C + (size_t)r0 * N + c0)       = make_float2(o00, o01);
                *(float2*)(C + (size_t)(r0 + 8) * N + c0) = make_float2(o10, o11);
            }
        }
    }
#undef LOAD_STAGE
}

// ---------------- all three projections in ONE launch ----------------
// CTAs [0, 2048): q = (v @ w_v^T + b_v)*SCALE   (K = V_DIM)
// CTAs [2048, 2176): k = l @ w_l^T + b_l        (K = L_DIM)
// CTAs [2176, 2304): val = l @ w_vl^T + b_vl    (K = L_DIM)
#define QPROJ_CTAS  ((B * NV / 128) * (EMBED / 128))     // 2048
#define KPROJ_CTAS  ((B * NLL / 128) * (EMBED / 128))    // 128
#define PROJ_CTAS   (QPROJ_CTAS + 2 * KPROJ_CTAS)        // 2304

__global__ __launch_bounds__(256, 2)
void gemm_proj_all(const __half* __restrict__ vh, const __half* __restrict__ lh,
                   const __half* __restrict__ wv, const float* __restrict__ b_v,
                   const __half* __restrict__ wl, const float* __restrict__ b_l,
                   const __half* __restrict__ wvl, const float* __restrict__ b_vl)
{
    const int cid = blockIdx.x;
    if (cid < QPROJ_CTAS) {
        const int bm = (cid >> 3) * 128;          // 8 n-tiles per m-row
        const int bn = (cid & 7) * 128;
        gemm_h_body<true>(vh, wv, b_v, g_q, EMBED, V_DIM, SCALE, bm, bn);
    } else {
        const int c = cid - QPROJ_CTAS;
        const int z = c >> 7;                     // 0 = k, 1 = val
        const int r = c & 127;
        const int bm = (r >> 3) * 128;
        const int bn = (r & 7) * 128;
        if (z == 0)
            gemm_h_body<true>(lh, wl, b_l, g_k, EMBED, L_DIM, 1.f, bm, bn);
        else
            gemm_h_body<true>(lh, wvl, b_vl, g_val, EMBED, L_DIM, 1.f, bm, bn);
    }
}

__global__ __launch_bounds__(256, 2)
void gemm_h_float(const __half* __restrict__ A, const __half* __restrict__ Bw,
                  const float* __restrict__ bias, float* __restrict__ C,
                  int N, int K, float alpha)
{
    gemm_h_body<false>(A, Bw, bias, C, N, K, alpha,
                       blockIdx.y * 128, blockIdx.x * 128);
}

// ---------------- tensor-core flash attention (fp16 in/out, R12 proven) ----------------
#define QSPLIT   4
#define QROWS    (NV / QSPLIT)
#define AT_KSTR  72
#define AT_VSTR  264
#define AT_SM_K  0
#define AT_SM_V  (256 * AT_KSTR * 2)
#define AT_SM_M  (AT_SM_V + 64 * AT_VSTR * 2)
#define AT_SMEM  (AT_SM_M + NLL * 4)

__global__ __launch_bounds__(256)
void attn_mma(const __half* __restrict__ q, const __half* __restrict__ kmat,
              const __half* __restrict__ vmat, const int* __restrict__ mask,
              __half* __restrict__ out)
{
    extern __shared__ char asmem[];
    __half* Ks = (__half*)(asmem + AT_SM_K);
    __half* Vt = (__half*)(asmem + AT_SM_V);
    float*  msf = (float*)(asmem + AT_SM_M);

    const int bh   = blockIdx.x;
    const int b    = bh >> 4;
    const int h    = bh & 15;
    const int sp   = blockIdx.y;
    const int tid  = threadIdx.x;
    const int warp = tid >> 5;
    const int lane = tid & 31;
    const int lq   = lane >> 2;
    const int lr   = lane & 3;

    for (int i = tid; i < 256 * 16; i += 256) {
        const int row = i >> 4;
        const int c4  = (i & 15) << 2;
        const size_t g = ((size_t)(b * NLL + row)) * EMBED + h * HD + c4;
        __half2 k0 = *(const __half2*)(kmat + g);
        __half2 k1 = *(const __half2*)(kmat + g + 2);
        __half2 v0 = *(const __half2*)(vmat + g);
        __half2 v1 = *(const __half2*)(vmat + g + 2);
        *(__half2*)(Ks + row * AT_KSTR + c4)     = k0;
        *(__half2*)(Ks + row * AT_KSTR + c4 + 2) = k1;
        Vt[(c4 + 0) * AT_VSTR + row] = __low2half(v0);
        Vt[(c4 + 1) * AT_VSTR + row] = __high2half(v0);
        Vt[(c4 + 2) * AT_VSTR + row] = __low2half(v1);
        Vt[(c4 + 3) * AT_VSTR + row] = __high2half(v1);
    }
    for (int i = tid; i < NLL; i += 256) msf[i] = mask[b * NLL + i] ? 1.f : 0.f;
    __syncthreads();

    for (int it = 0; it < QROWS / (16 * 8); it++) {
        const int r0 = sp * QROWS + (it * 8 + warp) * 16;
        const __half* qbase = q + ((size_t)(b * NV + r0)) * EMBED + h * HD;

        u32 qa[4][4];
#pragma unroll
        for (int c = 0; c < 4; c++) {
            const __half* p0 = qbase + (size_t)lq * EMBED + c * 16 + 2 * lr;
            const __half* p1 = qbase + (size_t)(lq + 8) * EMBED + c * 16 + 2 * lr;
            qa[c][0] = *(const u32*)(p0);
            qa[c][1] = *(const u32*)(p1);
            qa[c][2] = *(const u32*)(p0 + 8);
            qa[c][3] = *(const u32*)(p1 + 8);
        }

        float o[8][4];
#pragma unroll
        for (int jt = 0; jt < 8; jt++)
#pragma unroll
            for (int r = 0; r < 4; r++) o[jt][r] = 0.f;
        float sum0 = 0.f, sum1 = 0.f;

        for (int kb = 0; kb < 16; kb++) {
            float s0[4] = {0.f, 0.f, 0.f, 0.f};
            float s1[4] = {0.f, 0.f, 0.f, 0.f};
            const __half* kr = Ks + (kb * 16) * AT_KSTR;
#pragma unroll
            for (int c = 0; c < 4; c++) {
                u32 b0 = *(const u32*)(kr + lq * AT_KSTR + c * 16 + 2 * lr);
                u32 b1 = *(const u32*)(kr + lq * AT_KSTR + c * 16 + 2 * lr + 8);
                mma_f16(s0, qa[c][0], qa[c][1], qa[c][2], qa[c][3], b0, b1);
                u32 b2 = *(const u32*)(kr + (8 + lq) * AT_KSTR + c * 16 + 2 * lr);
                u32 b3 = *(const u32*)(kr + (8 + lq) * AT_KSTR + c * 16 + 2 * lr + 8);
                mma_f16(s1, qa[c][0], qa[c][1], qa[c][2], qa[c][3], b2, b3);
            }
            const int colb = kb * 16;
            const float m0 = msf[colb + 2 * lr];
            const float m1 = msf[colb + 2 * lr + 1];
            const float m2 = msf[colb + 8 + 2 * lr];
            const float m3 = msf[colb + 8 + 2 * lr + 1];
            const float p00 = __expf(s0[0]) * m0, p01 = __expf(s0[1]) * m1;
            const float p02 = __expf(s0[2]) * m0, p03 = __expf(s0[3]) * m1;
            const float p10 = __expf(s1[0]) * m2, p11 = __expf(s1[1]) * m3;
            const float p12 = __expf(s1[2]) * m2, p13 = __expf(s1[3]) * m3;
            sum0 += (p00 + p01) + (p10 + p11);
            sum1 += (p02 + p03) + (p12 + p13);
            const u32 a0 = f22u(p00, p01);
            const u32 a1 = f22u(p02, p03);
            const u32 a2 = f22u(p10, p11);
            const u32 a3 = f22u(p12, p13);

            const __half* vr = Vt + kb * 16;
#pragma unroll
            for (int jt = 0; jt < 8; jt++) {
                u32 vb0 = *(const u32*)(vr + (jt * 8 + lq) * AT_VSTR + 2 * lr);
                u32 vb1 = *(const u32*)(vr + (jt * 8 + lq) * AT_VSTR + 2 * lr + 8);
                mma_f16(o[jt], a0, a1, a2, a3, vb0, vb1);
            }
        }

        sum0 += __shfl_xor_sync(0xffffffffu, sum0, 1);
        sum0 += __shfl_xor_sync(0xffffffffu, sum0, 2);
        sum1 += __shfl_xor_sync(0xffffffffu, sum1, 1);
        sum1 += __shfl_xor_sync(0xffffffffu, sum1, 2);
        const float inv0 = __fdividef(1.f, sum0);
        const float inv1 = __fdividef(1.f, sum1);

        __half* ob = out + ((size_t)(b * NV + r0)) * EMBED + h * HD;
#pragma unroll
        for (int jt = 0; jt < 8; jt++) {
            *(u32*)(ob + (size_t)lq * EMBED + jt * 8 + 2 * lr)
                = f22u(o[jt][0] * inv0, o[jt][1] * inv0);
            *(u32*)(ob + (size_t)(lq + 8) * EMBED + jt * 8 + 2 * lr)
                = f22u(o[jt][2] * inv1, o[jt][3] * inv1);
        }
    }
}

// ---------------- launch ----------------
extern "C" void kernel_launch(void* const* d_in, const int* in_sizes, int n_in,
                              void* d_out, int out_size)
{
    const float* v     = (const float*)d_in[0];
    const float* l     = (const float*)d_in[1];
    const int*   amask = (const int*)  d_in[2];
    const float* w_v   = (const float*)d_in[3];
    const float* b_v   = (const float*)d_in[4];
    const float* w_l   = (const float*)d_in[5];
    const float* b_l   = (const float*)d_in[6];
    const float* w_vl  = (const float*)d_in[7];
    const float* b_vl  = (const float*)d_in[8];
    const float* w_out = (const float*)d_in[9];
    const float* b_out = (const float*)d_in[10];
    float* out = (float*)d_out;

    __half *vh, *lh, *wv, *wl, *wvl, *wo, *q, *k, *val, *att;
    cudaGetSymbolAddress((void**)&vh,  g_vh);
    cudaGetSymbolAddress((void**)&lh,  g_lh);
    cudaGetSymbolAddress((void**)&wv,  g_wv);
    cudaGetSymbolAddress((void**)&wl,  g_wl);
    cudaGetSymbolAddress((void**)&wvl, g_wvl);
    cudaGetSymbolAddress((void**)&wo,  g_wo);
    cudaGetSymbolAddress((void**)&q,   g_q);
    cudaGetSymbolAddress((void**)&k,   g_k);
    cudaGetSymbolAddress((void**)&val, g_val);
    cudaGetSymbolAddress((void**)&att, g_att);

    cudaFuncSetAttribute(attn_mma, cudaFuncAttributeMaxDynamicSharedMemorySize, AT_SMEM);
    cudaFuncSetAttribute(gemm_proj_all, cudaFuncAttributeMaxDynamicSharedMemorySize, GSMEM);
    cudaFuncSetAttribute(gemm_h_float, cudaFuncAttributeMaxDynamicSharedMemorySize, GSMEM);

    // one fused convert launch
    cvt_all<<<(CV5 + 255) / 256, 256>>>(v, l, w_v, w_l, w_vl, w_out);

    // all three projections in one launch (q tiles first, short tiles fill tail)
    gemm_proj_all<<<PROJ_CTAS, 256, GSMEM>>>(vh, lh, wv, b_v, wl, b_l, wvl, b_vl);

    // tensor-core flash attention
    attn_mma<<<dim3(B * HEADS, QSPLIT), 256, AT_SMEM>>>(q, k, val, amask, att);

    // out = att @ w_out^T + b_out (fp32 out)
    gemm_h_float<<<dim3(V_DIM / 128, (B * NV) / 128), 256, GSMEM>>>(
        att, wo, b_out, out, V_DIM, EMBED, 1.f);
}

// round 16
// speedup vs baseline: 1.0473x; 1.0058x over previous
#include <cuda_runtime.h>
#include <cuda_bf16.h>
#include <cuda_fp16.h>
#include <cstdint>

// ---------------- problem constants ----------------
#define B      8
#define NV     4096
#define NLL    256
#define V_DIM  1024
#define L_DIM  768
#define EMBED  1024
#define HEADS  16
#define HD     64
#define SCALE  0.125f

typedef unsigned long long u64;
typedef unsigned int u32;

// ---------------- scratch (fp16 end-to-end) ----------------
__device__ __align__(256) __half g_vh[(size_t)B * NV * V_DIM];
__device__ __align__(256) __half g_lh[(size_t)B * NLL * L_DIM];
__device__ __align__(256) __half g_wv[EMBED * V_DIM];
__device__ __align__(256) __half g_wl[EMBED * L_DIM];
__device__ __align__(256) __half g_wvl[EMBED * L_DIM];
__device__ __align__(256) __half g_wo[V_DIM * EMBED];
__device__ __align__(256) __half g_q[(size_t)B * NV * EMBED];
__device__ __align__(256) __half g_k[(size_t)B * NLL * EMBED];
__device__ __align__(256) __half g_val[(size_t)B * NLL * EMBED];
__device__ __align__(256) __half g_att[(size_t)B * NV * EMBED];

// ---------------- helpers ----------------
__device__ __forceinline__ void mma_f16(float d[4], u32 a0, u32 a1, u32 a2, u32 a3,
                                        u32 b0, u32 b1) {
    asm volatile(
        "mma.sync.aligned.m16n8k16.row.col.f32.f16.f16.f32 "
        "{%0,%1,%2,%3}, {%4,%5,%6,%7}, {%8,%9}, {%0,%1,%2,%3};"
        : "+f"(d[0]), "+f"(d[1]), "+f"(d[2]), "+f"(d[3])
        : "r"(a0), "r"(a1), "r"(a2), "r"(a3), "r"(b0), "r"(b1));
}
__device__ __forceinline__ void ldsm4(u32& r0, u32& r1, u32& r2, u32& r3, u32 addr) {
    asm volatile("ldmatrix.sync.aligned.m8n8.x4.shared.b16 {%0,%1,%2,%3}, [%4];"
                 : "=r"(r0), "=r"(r1), "=r"(r2), "=r"(r3) : "r"(addr));
}
__device__ __forceinline__ u32 f22u(float x, float y) {
    __half2 h = __float22half2_rn(make_float2(x, y));
    return *(u32*)&h;
}
__device__ __forceinline__ u32 smem_u32(const void* p) {
    u32 a;
    asm("{ .reg .u64 t; cvta.to.shared.u64 t, %1; cvt.u32.u64 %0, t; }"
        : "=r"(a) : "l"(p));
    return a;
}
__device__ __forceinline__ void cp16(u32 dst, const void* src) {
    asm volatile("cp.async.cg.shared.global [%0], [%1], 16;"
                 :: "r"(dst), "l"(src) : "memory");
}
__device__ __forceinline__ void cp_commit() {
    asm volatile("cp.async.commit_group;" ::: "memory");
}
template<int N>
__device__ __forceinline__ void cp_wait() {
    asm volatile("cp.async.wait_group %0;" :: "n"(N) : "memory");
}

// ---------------- fused pre-convert ----------------
#define NV_E   (B * NV * V_DIM)
#define NL_E   (B * NLL * L_DIM)
#define WV_E   (EMBED * V_DIM)
#define WL_E   (EMBED * L_DIM)
#define CV0    (NV_E / 4)
#define CV1    (CV0 + NL_E / 4)
#define CV2    (CV1 + WV_E / 4)
#define CV3    (CV2 + WL_E / 4)
#define CV4    (CV3 + WL_E / 4)
#define CV5    (CV4 + WV_E / 4)

__global__ __launch_bounds__(256)
void cvt_all(const float* __restrict__ v,  const float* __restrict__ l,
             const float* __restrict__ wv, const float* __restrict__ wl,
             const float* __restrict__ wvl, const float* __restrict__ wo)
{
    int i = blockIdx.x * 256 + threadIdx.x;
    if (i >= CV5) return;
    const float* src; __half* dst; int base;
    if      (i < CV0) { src = v;   dst = g_vh;  base = 0;   }
    else if (i < CV1) { src = l;   dst = g_lh;  base = CV0; }
    else if (i < CV2) { src = wv;  dst = g_wv;  base = CV1; }
    else if (i < CV3) { src = wl;  dst = g_wl;  base = CV2; }
    else if (i < CV4) { src = wvl; dst = g_wvl; base = CV3; }
    else              { src = wo;  dst = g_wo;  base = CV4; }
    const int j = (i - base) * 4;
    float4 f = *(const float4*)(src + j);
    *(__half2*)(dst + j)     = __float22half2_rn(make_float2(f.x, f.y));
    *(__half2*)(dst + j + 2) = __float22half2_rn(make_float2(f.z, f.w));
}

// ---------------- fp16 GEMM: 4-stage cp.async + ldmatrix, 2 CTAs/SM ----------------
#define HSTR 40
#define TILE_HALF (128 * HSTR)
#define STAGE_HALF (2 * TILE_HALF)
#define STAGES 4
#define GSMEM (STAGES * STAGE_HALF * 2)   // 81920

template<bool HALF_OUT>
__device__ __forceinline__
void gemm_h_body(const __half* __restrict__ A, const __half* __restrict__ Bw,
                 const float* __restrict__ bias, void* __restrict__ Cv,
                 int N, int K, float alpha, int bm, int bn)
{
    extern __shared__ __half hs[];
    const u32 sbase = smem_u32(hs);

    const int tid  = threadIdx.x;
    const int warp = tid >> 5;
    const int lane = tid & 31;
    const int wm = (warp >> 2) * 64;
    const int wn = (warp & 3) * 32;
    const int lq = lane >> 2;
    const int lr = lane & 3;

    // ldmatrix addressing: row (lane&15), col-half (lane>>4)*8
    const int mrow  = lane & 15;
    const int mcol8 = (lane >> 4) * 8;

    float acc[4][4][4];
#pragma unroll
    for (int i = 0; i < 4; i++)
#pragma unroll
        for (int j = 0; j < 4; j++)
#pragma unroll
            for (int r = 0; r < 4; r++) acc[i][j][r] = 0.f;

    const int row0 = tid >> 2;
    const int ch   = tid & 3;
    const __half* Ab = A  + (size_t)bm * K + ch * 8;
    const __half* Bb = Bw + (size_t)bn * K + ch * 8;

    const int NK = K / 32;

#define LOAD_STAGE(kt, s)                                                      \
    {                                                                          \
        const int _kh = (kt) * 32;                                             \
        _Pragma("unroll")                                                      \
        for (int _i = 0; _i < 2; _i++) {                                       \
            const int _r = row0 + _i * 64;                                     \
            cp16(sbase + ((s) * STAGE_HALF + _r * HSTR + ch * 8) * 2,          \
                 Ab + (size_t)_r * K + _kh);                                   \
            cp16(sbase + ((s) * STAGE_HALF + TILE_HALF + _r * HSTR + ch * 8) * 2, \
                 Bb + (size_t)_r * K + _kh);                                   \
        }                                                                      \
        cp_commit();                                                           \
    }

    LOAD_STAGE(0, 0)
    LOAD_STAGE(1, 1)
    LOAD_STAGE(2, 2)

    for (int kt = 0; kt < NK; kt++) {
        cp_wait<2>();
        __syncthreads();
        if (kt + 3 < NK) LOAD_STAGE(kt + 3, (kt + 3) % STAGES)

        const u32 stA = sbase + ((kt % STAGES) * STAGE_HALF) * 2;
        const u32 stB = stA + TILE_HALF * 2;
#pragma unroll
        for (int ks = 0; ks < 2; ks++) {
            const int kk = ks * 16 + mcol8;
            u32 a[4][4];
#pragma unroll
            for (int mt = 0; mt < 4; mt++)
                ldsm4(a[mt][0], a[mt][1], a[mt][2], a[mt][3],
                      stA + ((wm + mt * 16 + mrow) * HSTR + kk) * 2);
            u32 b[4][2];
#pragma unroll
            for (int p = 0; p < 2; p++)
                ldsm4(b[2 * p][0], b[2 * p + 1][0], b[2 * p][1], b[2 * p + 1][1],
                      stB + ((wn + p * 16 + mrow) * HSTR + kk) * 2);
#pragma unroll
            for (int mt = 0; mt < 4; mt++)
#pragma unroll
                for (int nt = 0; nt < 4; nt++)
                    mma_f16(acc[mt][nt], a[mt][0], a[mt][1], a[mt][2], a[mt][3],
                            b[nt][0], b[nt][1]);
        }
    }

    // epilogue
#pragma unroll
    for (int mt = 0; mt < 4; mt++) {
#pragma unroll
        for (int nt = 0; nt < 4; nt++) {
            const int r0 = bm + wm + mt * 16 + lq;
            const int c0 = bn + wn + nt * 8 + (lr << 1);
            const float bv0 = bias[c0];
            const float bv1 = bias[c0 + 1];
            const float o00 = alpha * (acc[mt][nt][0] + bv0);
            const float o01 = alpha * (acc[mt][nt][1] + bv1);
            const float o10 = alpha * (acc[mt][nt][2] + bv0);
            const float o11 = alpha * (acc[mt][nt][3] + bv1);
            if (HALF_OUT) {
                __half* C = (__half*)Cv;
                *(u32*)(C + (size_t)r0 * N + c0)       = f22u(o00, o01);
                *(u32*)(C + (size_t)(r0 + 8) * N + c0) = f22u(o10, o11);
            } else {
                float* C = (float*)Cv;
                *(float2*)(C + (size_t)r0 * N + c0)       = make_float2(o00, o01);
                *(float2*)(C + (size_t)(r0 + 8) * N + c0) = make_float2(o10, o11);
            }
        }
    }
#undef LOAD_STAGE
}

// ---------------- all three projections in ONE launch ----------------
#define QPROJ_CTAS  ((B * NV / 128) * (EMBED / 128))     // 2048
#define KPROJ_CTAS  ((B * NLL / 128) * (EMBED / 128))    // 128
#define PROJ_CTAS   (QPROJ_CTAS + 2 * KPROJ_CTAS)        // 2304

__global__ __launch_bounds__(256, 2)
void gemm_proj_all(const __half* __restrict__ vh, const __half* __restrict__ lh,
                   const __half* __restrict__ wv, const float* __restrict__ b_v,
                   const __half* __restrict__ wl, const float* __restrict__ b_l,
                   const __half* __restrict__ wvl, const float* __restrict__ b_vl)
{
    const int cid = blockIdx.x;
    if (cid < QPROJ_CTAS) {
        const int bm = (cid >> 3) * 128;
        const int bn = (cid & 7) * 128;
        gemm_h_body<true>(vh, wv, b_v, g_q, EMBED, V_DIM, SCALE, bm, bn);
    } else {
        const int c = cid - QPROJ_CTAS;
        const int z = c >> 7;
        const int r = c & 127;
        const int bm = (r >> 3) * 128;
        const int bn = (r & 7) * 128;
        if (z == 0)
            gemm_h_body<true>(lh, wl, b_l, g_k, EMBED, L_DIM, 1.f, bm, bn);
        else
            gemm_h_body<true>(lh, wvl, b_vl, g_val, EMBED, L_DIM, 1.f, bm, bn);
    }
}

__global__ __launch_bounds__(256, 2)
void gemm_h_float(const __half* __restrict__ A, const __half* __restrict__ Bw,
                  const float* __restrict__ bias, float* __restrict__ C,
                  int N, int K, float alpha)
{
    gemm_h_body<false>(A, Bw, bias, C, N, K, alpha,
                       blockIdx.y * 128, blockIdx.x * 128);
}

// ---------------- tensor-core flash attention (proven) ----------------
#define QSPLIT   4
#define QROWS    (NV / QSPLIT)
#define AT_KSTR  72
#define AT_VSTR  264
#define AT_SM_K  0
#define AT_SM_V  (256 * AT_KSTR * 2)
#define AT_SM_M  (AT_SM_V + 64 * AT_VSTR * 2)
#define AT_SMEM  (AT_SM_M + NLL * 4)

__global__ __launch_bounds__(256)
void attn_mma(const __half* __restrict__ q, const __half* __restrict__ kmat,
              const __half* __restrict__ vmat, const int* __restrict__ mask,
              __half* __restrict__ out)
{
    extern __shared__ char asmem[];
    __half* Ks = (__half*)(asmem + AT_SM_K);
    __half* Vt = (__half*)(asmem + AT_SM_V);
    float*  msf = (float*)(asmem + AT_SM_M);

    const int bh   = blockIdx.x;
    const int b    = bh >> 4;
    const int h    = bh & 15;
    const int sp   = blockIdx.y;
    const int tid  = threadIdx.x;
    const int warp = tid >> 5;
    const int lane = tid & 31;
    const int lq   = lane >> 2;
    const int lr   = lane & 3;

    for (int i = tid; i < 256 * 16; i += 256) {
        const int row = i >> 4;
        const int c4  = (i & 15) << 2;
        const size_t g = ((size_t)(b * NLL + row)) * EMBED + h * HD + c4;
        __half2 k0 = *(const __half2*)(kmat + g);
        __half2 k1 = *(const __half2*)(kmat + g + 2);
        __half2 v0 = *(const __half2*)(vmat + g);
        __half2 v1 = *(const __half2*)(vmat + g + 2);
        *(__half2*)(Ks + row * AT_KSTR + c4)     = k0;
        *(__half2*)(Ks + row * AT_KSTR + c4 + 2) = k1;
        Vt[(c4 + 0) * AT_VSTR + row] = __low2half(v0);
        Vt[(c4 + 1) * AT_VSTR + row] = __high2half(v0);
        Vt[(c4 + 2) * AT_VSTR + row] = __low2half(v1);
        Vt[(c4 + 3) * AT_VSTR + row] = __high2half(v1);
    }
    for (int i = tid; i < NLL; i += 256) msf[i] = mask[b * NLL + i] ? 1.f : 0.f;
    __syncthreads();

    for (int it = 0; it < QROWS / (16 * 8); it++) {
        const int r0 = sp * QROWS + (it * 8 + warp) * 16;
        const __half* qbase = q + ((size_t)(b * NV + r0)) * EMBED + h * HD;

        u32 qa[4][4];
#pragma unroll
        for (int c = 0; c < 4; c++) {
            const __half* p0 = qbase + (size_t)lq * EMBED + c * 16 + 2 * lr;
            const __half* p1 = qbase + (size_t)(lq + 8) * EMBED + c * 16 + 2 * lr;
            qa[c][0] = *(const u32*)(p0);
            qa[c][1] = *(const u32*)(p1);
            qa[c][2] = *(const u32*)(p0 + 8);
            qa[c][3] = *(const u32*)(p1 + 8);
        }

        float o[8][4];
#pragma unroll
        for (int jt = 0; jt < 8; jt++)
#pragma unroll
            for (int r = 0; r < 4; r++) o[jt][r] = 0.f;
        float sum0 = 0.f, sum1 = 0.f;

        for (int kb = 0; kb < 16; kb++) {
            float s0[4] = {0.f, 0.f, 0.f, 0.f};
            float s1[4] = {0.f, 0.f, 0.f, 0.f};
            const __half* kr = Ks + (kb * 16) * AT_KSTR;
#pragma unroll
            for (int c = 0; c < 4; c++) {
                u32 b0 = *(const u32*)(kr + lq * AT_KSTR + c * 16 + 2 * lr);
                u32 b1 = *(const u32*)(kr + lq * AT_KSTR + c * 16 + 2 * lr + 8);
                mma_f16(s0, qa[c][0], qa[c][1], qa[c][2], qa[c][3], b0, b1);
                u32 b2 = *(const u32*)(kr + (8 + lq) * AT_KSTR + c * 16 + 2 * lr);
                u32 b3 = *(const u32*)(kr + (8 + lq) * AT_KSTR + c * 16 + 2 * lr + 8);
                mma_f16(s1, qa[c][0], qa[c][1], qa[c][2], qa[c][3], b2, b3);
            }
            const int colb = kb * 16;
            const float m0 = msf[colb + 2 * lr];
            const float m1 = msf[colb + 2 * lr + 1];
            const float m2 = msf[colb + 8 + 2 * lr];
            const float m3 = msf[colb + 8 + 2 * lr + 1];
            const float p00 = __expf(s0[0]) * m0, p01 = __expf(s0[1]) * m1;
            const float p02 = __expf(s0[2]) * m0, p03 = __expf(s0[3]) * m1;
            const float p10 = __expf(s1[0]) * m2, p11 = __expf(s1[1]) * m3;
            const float p12 = __expf(s1[2]) * m2, p13 = __expf(s1[3]) * m3;
            sum0 += (p00 + p01) + (p10 + p11);
            sum1 += (p02 + p03) + (p12 + p13);
            const u32 a0 = f22u(p00, p01);
            const u32 a1 = f22u(p02, p03);
            const u32 a2 = f22u(p10, p11);
            const u32 a3 = f22u(p12, p13);

            const __half* vr = Vt + kb * 16;
#pragma unroll
            for (int jt = 0; jt < 8; jt++) {
                u32 vb0 = *(const u32*)(vr + (jt * 8 + lq) * AT_VSTR + 2 * lr);
                u32 vb1 = *(const u32*)(vr + (jt * 8 + lq) * AT_VSTR + 2 * lr + 8);
                mma_f16(o[jt], a0, a1, a2, a3, vb0, vb1);
            }
        }

        sum0 += __shfl_xor_sync(0xffffffffu, sum0, 1);
        sum0 += __shfl_xor_sync(0xffffffffu, sum0, 2);
        sum1 += __shfl_xor_sync(0xffffffffu, sum1, 1);
        sum1 += __shfl_xor_sync(0xffffffffu, sum1, 2);
        const float inv0 = __fdividef(1.f, sum0);
        const float inv1 = __fdividef(1.f, sum1);

        __half* ob = out + ((size_t)(b * NV + r0)) * EMBED + h * HD;
#pragma unroll
        for (int jt = 0; jt < 8; jt++) {
            *(u32*)(ob + (size_t)lq * EMBED + jt * 8 + 2 * lr)
                = f22u(o[jt][0] * inv0, o[jt][1] * inv0);
            *(u32*)(ob + (size_t)(lq + 8) * EMBED + jt * 8 + 2 * lr)
                = f22u(o[jt][2] * inv1, o[jt][3] * inv1);
        }
    }
}

// ---------------- launch ----------------
extern "C" void kernel_launch(void* const* d_in, const int* in_sizes, int n_in,
                              void* d_out, int out_size)
{
    const float* v     = (const float*)d_in[0];
    const float* l     = (const float*)d_in[1];
    const int*   amask = (const int*)  d_in[2];
    const float* w_v   = (const float*)d_in[3];
    const float* b_v   = (const float*)d_in[4];
    const float* w_l   = (const float*)d_in[5];
    const float* b_l   = (const float*)d_in[6];
    const float* w_vl  = (const float*)d_in[7];
    const float* b_vl  = (const float*)d_in[8];
    const float* w_out = (const float*)d_in[9];
    const float* b_out = (const float*)d_in[10];
    float* out = (float*)d_out;

    __half *vh, *lh, *wv, *wl, *wvl, *wo, *q, *k, *val, *att;
    cudaGetSymbolAddress((void**)&vh,  g_vh);
    cudaGetSymbolAddress((void**)&lh,  g_lh);
    cudaGetSymbolAddress((void**)&wv,  g_wv);
    cudaGetSymbolAddress((void**)&wl,  g_wl);
    cudaGetSymbolAddress((void**)&wvl, g_wvl);
    cudaGetSymbolAddress((void**)&wo,  g_wo);
    cudaGetSymbolAddress((void**)&q,   g_q);
    cudaGetSymbolAddress((void**)&k,   g_k);
    cudaGetSymbolAddress((void**)&val, g_val);
    cudaGetSymbolAddress((void**)&att, g_att);

    cudaFuncSetAttribute(attn_mma, cudaFuncAttributeMaxDynamicSharedMemorySize, AT_SMEM);
    cudaFuncSetAttribute(gemm_proj_all, cudaFuncAttributeMaxDynamicSharedMemorySize, GSMEM);
    cudaFuncSetAttribute(gemm_h_float, cudaFuncAttributeMaxDynamicSharedMemorySize, GSMEM);

    cvt_all<<<(CV5 + 255) / 256, 256>>>(v, l, w_v, w_l, w_vl, w_out);
    gemm_proj_all<<<PROJ_CTAS, 256, GSMEM>>>(vh, lh, wv, b_v, wl, b_l, wvl, b_vl);
    attn_mma<<<dim3(B * HEADS, QSPLIT), 256, AT_SMEM>>>(q, k, val, amask, att);
    gemm_h_float<<<dim3(V_DIM / 128, (B * NV) / 128), 256, GSMEM>>>(
        att, wo, b_out, out, V_DIM, EMBED, 1.f);
}

// round 17
// speedup vs baseline: 1.0547x; 1.0070x over previous
#include <cuda_runtime.h>
#include <cuda_bf16.h>
#include <cuda_fp16.h>
#include <cstdint>

// ---------------- problem constants ----------------
#define B      8
#define NV     4096
#define NLL    256
#define V_DIM  1024
#define L_DIM  768
#define EMBED  1024
#define HEADS  16
#define HD     64
#define SCALE  0.125f

typedef unsigned long long u64;
typedef unsigned int u32;

// ---------------- scratch (fp16 end-to-end) ----------------
__device__ __align__(256) __half g_vh[(size_t)B * NV * V_DIM];
__device__ __align__(256) __half g_lh[(size_t)B * NLL * L_DIM];
__device__ __align__(256) __half g_wv[EMBED * V_DIM];
__device__ __align__(256) __half g_wl[EMBED * L_DIM];
__device__ __align__(256) __half g_wvl[EMBED * L_DIM];
__device__ __align__(256) __half g_wo[V_DIM * EMBED];
__device__ __align__(256) __half g_q[(size_t)B * NV * EMBED];
__device__ __align__(256) __half g_k[(size_t)B * NLL * EMBED];
__device__ __align__(256) __half g_val[(size_t)B * NLL * EMBED];
__device__ __align__(256) __half g_att[(size_t)B * NV * EMBED];

// ---------------- helpers ----------------
__device__ __forceinline__ void mma_f16(float d[4], u32 a0, u32 a1, u32 a2, u32 a3,
                                        u32 b0, u32 b1) {
    asm volatile(
        "mma.sync.aligned.m16n8k16.row.col.f32.f16.f16.f32 "
        "{%0,%1,%2,%3}, {%4,%5,%6,%7}, {%8,%9}, {%0,%1,%2,%3};"
        : "+f"(d[0]), "+f"(d[1]), "+f"(d[2]), "+f"(d[3])
        : "r"(a0), "r"(a1), "r"(a2), "r"(a3), "r"(b0), "r"(b1));
}
__device__ __forceinline__ void ldsm4(u32& r0, u32& r1, u32& r2, u32& r3, u32 addr) {
    asm volatile("ldmatrix.sync.aligned.m8n8.x4.shared.b16 {%0,%1,%2,%3}, [%4];"
                 : "=r"(r0), "=r"(r1), "=r"(r2), "=r"(r3) : "r"(addr));
}
__device__ __forceinline__ u32 f22u(float x, float y) {
    __half2 h = __float22half2_rn(make_float2(x, y));
    return *(u32*)&h;
}
__device__ __forceinline__ u32 smem_u32(const void* p) {
    u32 a;
    asm("{ .reg .u64 t; cvta.to.shared.u64 t, %1; cvt.u32.u64 %0, t; }"
        : "=r"(a) : "l"(p));
    return a;
}
__device__ __forceinline__ void cp16(u32 dst, const void* src) {
    asm volatile("cp.async.cg.shared.global [%0], [%1], 16;"
                 :: "r"(dst), "l"(src) : "memory");
}
__device__ __forceinline__ void cp_commit() {
    asm volatile("cp.async.commit_group;" ::: "memory");
}
template<int N>
__device__ __forceinline__ void cp_wait() {
    asm volatile("cp.async.wait_group %0;" :: "n"(N) : "memory");
}

// ---------------- fused pre-convert ----------------
#define NV_E   (B * NV * V_DIM)
#define NL_E   (B * NLL * L_DIM)
#define WV_E   (EMBED * V_DIM)
#define WL_E   (EMBED * L_DIM)
#define CV0    (NV_E / 4)
#define CV1    (CV0 + NL_E / 4)
#define CV2    (CV1 + WV_E / 4)
#define CV3    (CV2 + WL_E / 4)
#define CV4    (CV3 + WL_E / 4)
#define CV5    (CV4 + WV_E / 4)

__global__ __launch_bounds__(256)
void cvt_all(const float* __restrict__ v,  const float* __restrict__ l,
             const float* __restrict__ wv, const float* __restrict__ wl,
             const float* __restrict__ wvl, const float* __restrict__ wo)
{
    int i = blockIdx.x * 256 + threadIdx.x;
    if (i >= CV5) return;
    const float* src; __half* dst; int base;
    if      (i < CV0) { src = v;   dst = g_vh;  base = 0;   }
    else if (i < CV1) { src = l;   dst = g_lh;  base = CV0; }
    else if (i < CV2) { src = wv;  dst = g_wv;  base = CV1; }
    else if (i < CV3) { src = wl;  dst = g_wl;  base = CV2; }
    else if (i < CV4) { src = wvl; dst = g_wvl; base = CV3; }
    else              { src = wo;  dst = g_wo;  base = CV4; }
    const int j = (i - base) * 4;
    float4 f = *(const float4*)(src + j);
    *(__half2*)(dst + j)     = __float22half2_rn(make_float2(f.x, f.y));
    *(__half2*)(dst + j + 2) = __float22half2_rn(make_float2(f.z, f.w));
}

// ---------------- fp16 GEMM: 4-stage cp.async + ldmatrix (R16, at HW floor) ----------------
#define HSTR 40
#define TILE_HALF (128 * HSTR)
#define STAGE_HALF (2 * TILE_HALF)
#define STAGES 4
#define GSMEM (STAGES * STAGE_HALF * 2)

template<bool HALF_OUT>
__device__ __forceinline__
void gemm_h_body(const __half* __restrict__ A, const __half* __restrict__ Bw,
                 const float* __restrict__ bias, void* __restrict__ Cv,
                 int N, int K, float alpha, int bm, int bn)
{
    extern __shared__ __half hs[];
    const u32 sbase = smem_u32(hs);

    const int tid  = threadIdx.x;
    const int warp = tid >> 5;
    const int lane = tid & 31;
    const int wm = (warp >> 2) * 64;
    const int wn = (warp & 3) * 32;
    const int lq = lane >> 2;
    const int lr = lane & 3;
    const int mrow  = lane & 15;
    const int mcol8 = (lane >> 4) * 8;

    float acc[4][4][4];
#pragma unroll
    for (int i = 0; i < 4; i++)
#pragma unroll
        for (int j = 0; j < 4; j++)
#pragma unroll
            for (int r = 0; r < 4; r++) acc[i][j][r] = 0.f;

    const int row0 = tid >> 2;
    const int ch   = tid & 3;
    const __half* Ab = A  + (size_t)bm * K + ch * 8;
    const __half* Bb = Bw + (size_t)bn * K + ch * 8;

    const int NK = K / 32;

#define LOAD_STAGE(kt, s)                                                      \
    {                                                                          \
        const int _kh = (kt) * 32;                                             \
        _Pragma("unroll")                                                      \
        for (int _i = 0; _i < 2; _i++) {                                       \
            const int _r = row0 + _i * 64;                                     \
            cp16(sbase + ((s) * STAGE_HALF + _r * HSTR + ch * 8) * 2,          \
                 Ab + (size_t)_r * K + _kh);                                   \
            cp16(sbase + ((s) * STAGE_HALF + TILE_HALF + _r * HSTR + ch * 8) * 2, \
                 Bb + (size_t)_r * K + _kh);                                   \
        }                                                                      \
        cp_commit();                                                           \
    }

    LOAD_STAGE(0, 0)
    LOAD_STAGE(1, 1)
    LOAD_STAGE(2, 2)

    for (int kt = 0; kt < NK; kt++) {
        cp_wait<2>();
        __syncthreads();
        if (kt + 3 < NK) LOAD_STAGE(kt + 3, (kt + 3) % STAGES)

        const u32 stA = sbase + ((kt % STAGES) * STAGE_HALF) * 2;
        const u32 stB = stA + TILE_HALF * 2;
#pragma unroll
        for (int ks = 0; ks < 2; ks++) {
            const int kk = ks * 16 + mcol8;
            u32 a[4][4];
#pragma unroll
            for (int mt = 0; mt < 4; mt++)
                ldsm4(a[mt][0], a[mt][1], a[mt][2], a[mt][3],
                      stA + ((wm + mt * 16 + mrow) * HSTR + kk) * 2);
            u32 b[4][2];
#pragma unroll
            for (int p = 0; p < 2; p++)
                ldsm4(b[2 * p][0], b[2 * p + 1][0], b[2 * p][1], b[2 * p + 1][1],
                      stB + ((wn + p * 16 + mrow) * HSTR + kk) * 2);
#pragma unroll
            for (int mt = 0; mt < 4; mt++)
#pragma unroll
                for (int nt = 0; nt < 4; nt++)
                    mma_f16(acc[mt][nt], a[mt][0], a[mt][1], a[mt][2], a[mt][3],
                            b[nt][0], b[nt][1]);
        }
    }

#pragma unroll
    for (int mt = 0; mt < 4; mt++) {
#pragma unroll
        for (int nt = 0; nt < 4; nt++) {
            const int r0 = bm + wm + mt * 16 + lq;
            const int c0 = bn + wn + nt * 8 + (lr << 1);
            const float bv0 = bias[c0];
            const float bv1 = bias[c0 + 1];
            const float o00 = alpha * (acc[mt][nt][0] + bv0);
            const float o01 = alpha * (acc[mt][nt][1] + bv1);
            const float o10 = alpha * (acc[mt][nt][2] + bv0);
            const float o11 = alpha * (acc[mt][nt][3] + bv1);
            if (HALF_OUT) {
                __half* C = (__half*)Cv;
                *(u32*)(C + (size_t)r0 * N + c0)       = f22u(o00, o01);
                *(u32*)(C + (size_t)(r0 + 8) * N + c0) = f22u(o10, o11);
            } else {
                float* C = (float*)Cv;
                *(float2*)(C + (size_t)r0 * N + c0)       = make_float2(o00, o01);
                *(float2*)(C + (size_t)(r0 + 8) * N + c0) = make_float2(o10, o11);
            }
        }
    }
#undef LOAD_STAGE
}

// ---------------- all three projections in ONE launch ----------------
#define QPROJ_CTAS  ((B * NV / 128) * (EMBED / 128))
#define KPROJ_CTAS  ((B * NLL / 128) * (EMBED / 128))
#define PROJ_CTAS   (QPROJ_CTAS + 2 * KPROJ_CTAS)

__global__ __launch_bounds__(256, 2)
void gemm_proj_all(const __half* __restrict__ vh, const __half* __restrict__ lh,
                   const __half* __restrict__ wv, const float* __restrict__ b_v,
                   const __half* __restrict__ wl, const float* __restrict__ b_l,
                   const __half* __restrict__ wvl, const float* __restrict__ b_vl)
{
    const int cid = blockIdx.x;
    if (cid < QPROJ_CTAS) {
        const int bm = (cid >> 3) * 128;
        const int bn = (cid & 7) * 128;
        gemm_h_body<true>(vh, wv, b_v, g_q, EMBED, V_DIM, SCALE, bm, bn);
    } else {
        const int c = cid - QPROJ_CTAS;
        const int z = c >> 7;
        const int r = c & 127;
        const int bm = (r >> 3) * 128;
        const int bn = (r & 7) * 128;
        if (z == 0)
            gemm_h_body<true>(lh, wl, b_l, g_k, EMBED, L_DIM, 1.f, bm, bn);
        else
            gemm_h_body<true>(lh, wvl, b_vl, g_val, EMBED, L_DIM, 1.f, bm, bn);
    }
}

__global__ __launch_bounds__(256, 2)
void gemm_h_float(const __half* __restrict__ A, const __half* __restrict__ Bw,
                  const float* __restrict__ bias, float* __restrict__ C,
                  int N, int K, float alpha)
{
    gemm_h_body<false>(A, Bw, bias, C, N, K, alpha,
                       blockIdx.y * 128, blockIdx.x * 128);
}

// ---------------- tensor-core flash attention: 32-row warp tiles ----------------
#define QSPLIT   8
#define QROWS    (NV / QSPLIT)      // 512
#define AT_KSTR  72
#define AT_VSTR  264
#define AT_SM_K  0
#define AT_SM_V  (256 * AT_KSTR * 2)
#define AT_SM_M  (AT_SM_V + 64 * AT_VSTR * 2)
#define AT_SMEM  (AT_SM_M + NLL * 4)

__global__ __launch_bounds__(256)
void attn_mma(const __half* __restrict__ q, const __half* __restrict__ kmat,
              const __half* __restrict__ vmat, const int* __restrict__ mask,
              __half* __restrict__ out)
{
    extern __shared__ char asmem[];
    __half* Ks = (__half*)(asmem + AT_SM_K);
    __half* Vt = (__half*)(asmem + AT_SM_V);
    float*  msf = (float*)(asmem + AT_SM_M);

    const int bh   = blockIdx.x;
    const int b    = bh >> 4;
    const int h    = bh & 15;
    const int sp   = blockIdx.y;
    const int tid  = threadIdx.x;
    const int warp = tid >> 5;
    const int lane = tid & 31;
    const int lq   = lane >> 2;
    const int lr   = lane & 3;

    for (int i = tid; i < 256 * 16; i += 256) {
        const int row = i >> 4;
        const int c4  = (i & 15) << 2;
        const size_t g = ((size_t)(b * NLL + row)) * EMBED + h * HD + c4;
        __half2 k0 = *(const __half2*)(kmat + g);
        __half2 k1 = *(const __half2*)(kmat + g + 2);
        __half2 v0 = *(const __half2*)(vmat + g);
        __half2 v1 = *(const __half2*)(vmat + g + 2);
        *(__half2*)(Ks + row * AT_KSTR + c4)     = k0;
        *(__half2*)(Ks + row * AT_KSTR + c4 + 2) = k1;
        Vt[(c4 + 0) * AT_VSTR + row] = __low2half(v0);
        Vt[(c4 + 1) * AT_VSTR + row] = __high2half(v0);
        Vt[(c4 + 2) * AT_VSTR + row] = __low2half(v1);
        Vt[(c4 + 3) * AT_VSTR + row] = __high2half(v1);
    }
    for (int i = tid; i < NLL; i += 256) msf[i] = mask[b * NLL + i] ? 1.f : 0.f;
    __syncthreads();

    // per iteration: 8 warps x 32 rows = 256 rows; QROWS/256 = 2 iterations
    for (int it = 0; it < QROWS / 256; it++) {
        const int r0 = sp * QROWS + it * 256 + warp * 32;
        const __half* qbase = q + ((size_t)(b * NV + r0)) * EMBED + h * HD;

        // Q fragments for two 16-row tiles
        u32 qa[2][4][4];
#pragma unroll
        for (int t = 0; t < 2; t++)
#pragma unroll
            for (int c = 0; c < 4; c++) {
                const __half* p0 = qbase + (size_t)(t * 16 + lq) * EMBED + c * 16 + 2 * lr;
                const __half* p1 = qbase + (size_t)(t * 16 + lq + 8) * EMBED + c * 16 + 2 * lr;
                qa[t][c][0] = *(const u32*)(p0);
                qa[t][c][1] = *(const u32*)(p1);
                qa[t][c][2] = *(const u32*)(p0 + 8);
                qa[t][c][3] = *(const u32*)(p1 + 8);
            }

        float o[2][8][4];
#pragma unroll
        for (int t = 0; t < 2; t++)
#pragma unroll
            for (int jt = 0; jt < 8; jt++)
#pragma unroll
                for (int r = 0; r < 4; r++) o[t][jt][r] = 0.f;
        float sum0[2] = {0.f, 0.f}, sum1[2] = {0.f, 0.f};

        for (int kb = 0; kb < 16; kb++) {
            float s[2][2][4];
#pragma unroll
            for (int t = 0; t < 2; t++)
#pragma unroll
                for (int u = 0; u < 2; u++)
#pragma unroll
                    for (int r = 0; r < 4; r++) s[t][u][r] = 0.f;

            const __half* kr = Ks + (kb * 16) * AT_KSTR;
#pragma unroll
            for (int c = 0; c < 4; c++) {
                // K fragments shared across both q-tiles
                u32 b0 = *(const u32*)(kr + lq * AT_KSTR + c * 16 + 2 * lr);
                u32 b1 = *(const u32*)(kr + lq * AT_KSTR + c * 16 + 2 * lr + 8);
                u32 b2 = *(const u32*)(kr + (8 + lq) * AT_KSTR + c * 16 + 2 * lr);
                u32 b3 = *(const u32*)(kr + (8 + lq) * AT_KSTR + c * 16 + 2 * lr + 8);
#pragma unroll
                for (int t = 0; t < 2; t++) {
                    mma_f16(s[t][0], qa[t][c][0], qa[t][c][1], qa[t][c][2], qa[t][c][3], b0, b1);
                    mma_f16(s[t][1], qa[t][c][0], qa[t][c][1], qa[t][c][2], qa[t][c][3], b2, b3);
                }
            }

            const int colb = kb * 16;
            const float m0 = msf[colb + 2 * lr];
            const float m1 = msf[colb + 2 * lr + 1];
            const float m2 = msf[colb + 8 + 2 * lr];
            const float m3 = msf[colb + 8 + 2 * lr + 1];

            u32 a[2][4];
#pragma unroll
            for (int t = 0; t < 2; t++) {
                const float p00 = __expf(s[t][0][0]) * m0, p01 = __expf(s[t][0][1]) * m1;
                const float p02 = __expf(s[t][0][2]) * m0, p03 = __expf(s[t][0][3]) * m1;
                const float p10 = __expf(s[t][1][0]) * m2, p11 = __expf(s[t][1][1]) * m3;
                const float p12 = __expf(s[t][1][2]) * m2, p13 = __expf(s[t][1][3]) * m3;
                sum0[t] += (p00 + p01) + (p10 + p11);
                sum1[t] += (p02 + p03) + (p12 + p13);
                a[t][0] = f22u(p00, p01);
                a[t][1] = f22u(p02, p03);
                a[t][2] = f22u(p10, p11);
                a[t][3] = f22u(p12, p13);
            }

            const __half* vr = Vt + kb * 16;
#pragma unroll
            for (int jt = 0; jt < 8; jt++) {
                // V fragments shared across both q-tiles
                u32 vb0 = *(const u32*)(vr + (jt * 8 + lq) * AT_VSTR + 2 * lr);
                u32 vb1 = *(const u32*)(vr + (jt * 8 + lq) * AT_VSTR + 2 * lr + 8);
                mma_f16(o[0][jt], a[0][0], a[0][1], a[0][2], a[0][3], vb0, vb1);
                mma_f16(o[1][jt], a[1][0], a[1][1], a[1][2], a[1][3], vb0, vb1);
            }
        }

#pragma unroll
        for (int t = 0; t < 2; t++) {
            float s0 = sum0[t], s1 = sum1[t];
            s0 += __shfl_xor_sync(0xffffffffu, s0, 1);
            s0 += __shfl_xor_sync(0xffffffffu, s0, 2);
            s1 += __shfl_xor_sync(0xffffffffu, s1, 1);
            s1 += __shfl_xor_sync(0xffffffffu, s1, 2);
            const float inv0 = __fdividef(1.f, s0);
            const float inv1 = __fdividef(1.f, s1);

            __half* ob = out + ((size_t)(b * NV + r0 + t * 16)) * EMBED + h * HD;
#pragma unroll
            for (int jt = 0; jt < 8; jt++) {
                *(u32*)(ob + (size_t)lq * EMBED + jt * 8 + 2 * lr)
                    = f22u(o[t][jt][0] * inv0, o[t][jt][1] * inv0);
                *(u32*)(ob + (size_t)(lq + 8) * EMBED + jt * 8 + 2 * lr)
                    = f22u(o[t][jt][2] * inv1, o[t][jt][3] * inv1);
            }
        }
    }
}

// ---------------- launch ----------------
extern "C" void kernel_launch(void* const* d_in, const int* in_sizes, int n_in,
                              void* d_out, int out_size)
{
    const float* v     = (const float*)d_in[0];
    const float* l     = (const float*)d_in[1];
    const int*   amask = (const int*)  d_in[2];
    const float* w_v   = (const float*)d_in[3];
    const float* b_v   = (const float*)d_in[4];
    const float* w_l   = (const float*)d_in[5];
    const float* b_l   = (const float*)d_in[6];
    const float* w_vl  = (const float*)d_in[7];
    const float* b_vl  = (const float*)d_in[8];
    const float* w_out = (const float*)d_in[9];
    const float* b_out = (const float*)d_in[10];
    float* out = (float*)d_out;

    __half *vh, *lh, *wv, *wl, *wvl, *wo, *q, *k, *val, *att;
    cudaGetSymbolAddress((void**)&vh,  g_vh);
    cudaGetSymbolAddress((void**)&lh,  g_lh);
    cudaGetSymbolAddress((void**)&wv,  g_wv);
    cudaGetSymbolAddress((void**)&wl,  g_wl);
    cudaGetSymbolAddress((void**)&wvl, g_wvl);
    cudaGetSymbolAddress((void**)&wo,  g_wo);
    cudaGetSymbolAddress((void**)&q,   g_q);
    cudaGetSymbolAddress((void**)&k,   g_k);
    cudaGetSymbolAddress((void**)&val, g_val);
    cudaGetSymbolAddress((void**)&att, g_att);

    cudaFuncSetAttribute(attn_mma, cudaFuncAttributeMaxDynamicSharedMemorySize, AT_SMEM);
    cudaFuncSetAttribute(gemm_proj_all, cudaFuncAttributeMaxDynamicSharedMemorySize, GSMEM);
    cudaFuncSetAttribute(gemm_h_float, cudaFuncAttributeMaxDynamicSharedMemorySize, GSMEM);

    cvt_all<<<(CV5 + 255) / 256, 256>>>(v, l, w_v, w_l, w_vl, w_out);
    gemm_proj_all<<<PROJ_CTAS, 256, GSMEM>>>(vh, lh, wv, b_v, wl, b_l, wvl, b_vl);
    attn_mma<<<dim3(B * HEADS, QSPLIT), 256, AT_SMEM>>>(q, k, val, amask, att);
    gemm_h_float<<<dim3(V_DIM / 128, (B * NV) / 128), 256, GSMEM>>>(
        att, wo, b_out, out, V_DIM, EMBED, 1.f);
}